// round 1
// baseline (speedup 1.0000x reference)
#include <cuda_runtime.h>
#include <cuda_bf16.h>
#include <math.h>

// ---------------------------------------------------------------------------
// TDNN (x-vector) forward.
// Layout convention: activations stored [B, T, C] row-major (C contiguous).
// Splice(offsets) + conv1x1 == GEMM with permuted weights reading time-shifted
// contiguous rows. BatchNorm folded into the NEXT layer's weights.
// ---------------------------------------------------------------------------

#define BATCH 32
#define TT0 2048
#define TT1 2044   // after splice (0,1,2,3,4)
#define TT2 2040   // after splice (0,2,4)
#define TT3 2034   // after splice (0,3,6)

#define N1 (BATCH*TT1)   // 65408
#define N2 (BATCH*TT2)   // 65280
#define N3 (BATCH*TT3)   // 65088

// ------------------------- scratch (static device memory) ------------------
__device__ float g_bufA[(size_t)BATCH * TT1 * 512];   // 134 MB
__device__ float g_bufB[(size_t)BATCH * TT1 * 512];   // 134 MB
__device__ float g_buf5[(size_t)BATCH * TT3 * 1500];  // 390 MB

__device__ float g_wT1[100 * 512];
__device__ float g_wT2[1536 * 512];
__device__ float g_wT3[1536 * 512];
__device__ float g_wT4[512 * 512];
__device__ float g_wT5[512 * 1500];
__device__ float g_wF [1536 * 512];     // folded weights (reused per stage; >= 512*1500)
__device__ float g_bF [1500];           // folded bias

__device__ float g_sum  [1536];
__device__ float g_sumsq[1536];
__device__ float g_alpha[512];
__device__ float g_delta[512];

__device__ float g_pcS [BATCH * 1500];
__device__ float g_pcQ [BATCH * 1500];
__device__ float g_pool[BATCH * 3000];
__device__ float g_fc1 [BATCH * 512];
__device__ float g_fc1n[BATCH * 512];
__device__ float g_fc2 [BATCH * 512];

// ------------------------- tiny utility kernels ----------------------------
__global__ void k_zero(float* p, int n) {
    int i = blockIdx.x * blockDim.x + threadIdx.x;
    if (i < n) p[i] = 0.f;
}

// h1_w [512,100], k = f*5+c  ->  wT[(c*20+f)*512 + m]
__global__ void k_permute_w1(const float* __restrict__ w, float* __restrict__ wT) {
    int i = blockIdx.x * blockDim.x + threadIdx.x;
    if (i >= 512 * 100) return;
    int m = i / 100, k = i % 100;
    int f = k / 5, c = k % 5;
    wT[(c * 20 + f) * 512 + m] = w[i];
}

// h{2,3}_w [512,1536], k = f*3+c  ->  wT[(c*512+f)*512 + m]
__global__ void k_permute_w23(const float* __restrict__ w, float* __restrict__ wT) {
    int i = blockIdx.x * blockDim.x + threadIdx.x;
    if (i >= 512 * 1536) return;
    int m = i / 1536, k = i % 1536;
    int f = k / 3, c = k % 3;
    wT[(c * 512 + f) * 512 + m] = w[i];
}

// generic transpose w [M,K] -> wT [K,M]
__global__ void k_transpose(const float* __restrict__ w, float* __restrict__ wT, int M, int K) {
    int i = blockIdx.x * blockDim.x + threadIdx.x;
    if (i >= M * K) return;
    int m = i / K, k = i % K;
    wT[k * M + m] = w[i];
}

// per-channel BN params from raw sums: alpha = rsqrt(var+eps)*gamma,
// delta = beta - mean*alpha
__global__ void k_bn_params(const float* __restrict__ sum, const float* __restrict__ sumsq,
                            float invN, const float* __restrict__ gamma,
                            const float* __restrict__ beta, int F,
                            float* __restrict__ alpha, float* __restrict__ delta) {
    int f = blockIdx.x * blockDim.x + threadIdx.x;
    if (f >= F) return;
    float mean = sum[f] * invN;
    float var  = sumsq[f] * invN - mean * mean;
    float s    = rsqrtf(var + 1e-5f);
    float g = gamma ? gamma[f] : 1.f;
    float b = beta  ? beta[f]  : 0.f;
    float a = s * g;
    alpha[f] = a;
    delta[f] = b - mean * a;
}

// wF[k*M+m] = wT[k*M+m] * alpha[k % F]
__global__ void k_fold_w(const float* __restrict__ wT, float* __restrict__ wF,
                         const float* __restrict__ alpha, int F, int K, int M) {
    int i = blockIdx.x * blockDim.x + threadIdx.x;
    if (i >= K * M) return;
    int k = i / M;
    wF[i] = wT[i] * alpha[k % F];
}

// bF[m] = bias[m] + sum_k wT[k*M+m] * delta[k % F]
__global__ void k_fold_b(const float* __restrict__ wT, const float* __restrict__ bias,
                         float* __restrict__ bF, const float* __restrict__ delta,
                         int F, int K, int M) {
    int m = blockIdx.x * blockDim.x + threadIdx.x;
    if (m >= M) return;
    float acc = bias[m];
    for (int k = 0; k < K; k++)
        acc += wT[k * M + m] * delta[k % F];
    bF[m] = acc;
}

// per-channel sum/sumsq over [N, M]
__global__ void k_stats(const float* __restrict__ X, int N, int M,
                        float* __restrict__ sum, float* __restrict__ sumsq) {
    int c = blockIdx.x * blockDim.x + threadIdx.x;
    if (c >= M) return;
    int rows_per = (N + gridDim.y - 1) / gridDim.y;
    int r0 = blockIdx.y * rows_per;
    int r1 = min(N, r0 + rows_per);
    float s = 0.f, q = 0.f;
    for (int r = r0; r < r1; r++) {
        float v = X[(size_t)r * M + c];
        s += v; q += v * v;
    }
    atomicAdd(&sum[c], s);
    atomicAdd(&sumsq[c], q);
}

// per-(b,c) sum/sumsq over time for stage-5 output [B, T, M]
__global__ void k_pcstats(const float* __restrict__ X, int T, int M,
                          float* __restrict__ pcS, float* __restrict__ pcQ) {
    int c = blockIdx.x * blockDim.x + threadIdx.x;
    if (c >= M) return;
    int b = blockIdx.y;
    int tper = (T + gridDim.z - 1) / gridDim.z;
    int t0 = blockIdx.z * tper;
    int t1 = min(T, t0 + tper);
    float s = 0.f, q = 0.f;
    for (int t = t0; t < t1; t++) {
        float v = X[((size_t)(b * T + t)) * M + c];
        s += v; q += v * v;
    }
    atomicAdd(&pcS[b * M + c], s);
    atomicAdd(&pcQ[b * M + c], q);
}

// bn5 + stats pooling, fully analytic from per-(b,c) sums
__global__ void k_pool(const float* __restrict__ pcS, const float* __restrict__ pcQ,
                       int T, int M, const float* __restrict__ gamma,
                       const float* __restrict__ beta, float* __restrict__ pooled) {
    int c = blockIdx.x * blockDim.x + threadIdx.x;
    if (c >= M) return;
    float gs = 0.f, gq = 0.f;
    for (int b = 0; b < BATCH; b++) { gs += pcS[b * M + c]; gq += pcQ[b * M + c]; }
    float Nf = (float)(BATCH * T);
    float mean = gs / Nf;
    float var  = gq / Nf - mean * mean;
    float s    = rsqrtf(var + 1e-5f);
    float a    = s * gamma[c];
    float bt   = beta[c];
    float Tf   = (float)T;
    for (int b = 0; b < BATCH; b++) {
        float S1 = pcS[b * M + c], S2 = pcQ[b * M + c];
        float mt = S1 / Tf;
        float vt = (S2 - S1 * S1 / Tf) / (Tf - 1.f);       // unbiased (torch.std)
        pooled[b * 2 * M + c]     = (mt - mean) * a + bt;
        pooled[b * 2 * M + M + c] = sqrtf(fmaxf(vt, 0.f)) * fabsf(a);
    }
}

// small FC: Y[b,m] = relu6( X[b,:] . W[m,:] + bias[m] ), one block per m
__global__ void k_fc(const float* __restrict__ X, const float* __restrict__ W,
                     const float* __restrict__ bias, float* __restrict__ Y,
                     int K, int M) {
    __shared__ float red[4][32];
    int m = blockIdx.x;
    int tid = threadIdx.x;
    float acc[BATCH];
#pragma unroll
    for (int b = 0; b < BATCH; b++) acc[b] = 0.f;
    for (int k = tid; k < K; k += blockDim.x) {
        float w = W[m * K + k];
#pragma unroll
        for (int b = 0; b < BATCH; b++) acc[b] += X[b * K + k] * w;
    }
#pragma unroll
    for (int b = 0; b < BATCH; b++) {
        float v = acc[b];
#pragma unroll
        for (int o = 16; o; o >>= 1) v += __shfl_down_sync(0xffffffffu, v, o);
        if ((tid & 31) == 0) red[tid >> 5][b] = v;
    }
    __syncthreads();
    if (tid < BATCH) {
        float v = red[0][tid] + red[1][tid] + red[2][tid] + red[3][tid];
        v += bias[m];
        v = fminf(fmaxf(v, 0.f), 6.f);
        Y[tid * M + m] = v;
    }
}

// BatchNorm over batch dim on [B, M] (biased var)
__global__ void k_bnc(const float* __restrict__ X, const float* __restrict__ gamma,
                      const float* __restrict__ beta, float* __restrict__ Y, int M) {
    int j = blockIdx.x * blockDim.x + threadIdx.x;
    if (j >= M) return;
    float s = 0.f, q = 0.f;
    for (int b = 0; b < BATCH; b++) { float v = X[b * M + j]; s += v; q += v * v; }
    float mean = s / (float)BATCH;
    float var  = q / (float)BATCH - mean * mean;
    float sc   = rsqrtf(var + 1e-5f) * gamma[j];
    for (int b = 0; b < BATCH; b++)
        Y[b * M + j] = (X[b * M + j] - mean) * sc + beta[j];
}

// ------------------------- main GEMM (splice-aware conv1x1) -----------------
// Out[r, m] = act( sum_c sum_f W[(c*F+f)*M + m] * In[(b*Tin + t + c*step)*F + f] + bias[m] )
// r = b*Tout + t, r < N.  Tile 128x128, BK=16, 256 threads, 8x8 per thread.
__global__ __launch_bounds__(256, 2)
void gemm_conv(const float* __restrict__ In, const float* __restrict__ W,
               const float* __restrict__ bias, float* __restrict__ Out,
               int Tin, int Tout, int F, int NC, int step,
               int M, int N, float actmax) {
    __shared__ float As[16][128];
    __shared__ float Bs[16][128];

    const int tid  = threadIdx.x;
    const int row0 = blockIdx.x * 128;
    const int col0 = blockIdx.y * 128;

    // A-load mapping: row = tid>>1 (0..127), k-half = (tid&1)*8
    const int arow = tid >> 1;
    const int ak0  = (tid & 1) * 8;
    const int r    = row0 + arow;
    const bool rvalid = (r < N);
    int b = 0, t = 0;
    if (rvalid) { b = r / Tout; t = r - b * Tout; }
    const float* rowBase = In + (size_t)(b * Tin + t) * F;

    // B-load mapping: k = tid>>4 (0..15), m-group = (tid&15)*8
    const int bk  = tid >> 4;
    const int bm0 = (tid & 15) * 8;

    // compute fragment coords
    const int tr = (tid >> 4) * 8;
    const int tc = (tid & 15) * 8;

    float acc[8][8];
#pragma unroll
    for (int i = 0; i < 8; i++)
#pragma unroll
        for (int j = 0; j < 8; j++) acc[i][j] = 0.f;

    for (int c = 0; c < NC; c++) {
        const float* Abase = rowBase + (size_t)(c * step) * F;
        const int kcbase = c * F;
        for (int k0 = 0; k0 < F; k0 += 16) {
            // stage A tile (transposed: As[k][row])
#pragma unroll
            for (int i = 0; i < 8; i++) {
                int kk = k0 + ak0 + i;
                float v = 0.f;
                if (rvalid && kk < F) v = Abase[kk];
                As[ak0 + i][arow] = v;
            }
            // stage B tile
            {
                int kk = k0 + bk;
                const float* wrow = W + (size_t)(kcbase + kk) * M;
#pragma unroll
                for (int j = 0; j < 8; j++) {
                    int m = col0 + bm0 + j;
                    float v = 0.f;
                    if (kk < F && m < M) v = wrow[m];
                    Bs[bk][bm0 + j] = v;
                }
            }
            __syncthreads();
#pragma unroll
            for (int kk = 0; kk < 16; kk++) {
                float a[8], bb[8];
#pragma unroll
                for (int i = 0; i < 8; i++) a[i] = As[kk][tr + i];
#pragma unroll
                for (int j = 0; j < 8; j++) bb[j] = Bs[kk][tc + j];
#pragma unroll
                for (int i = 0; i < 8; i++)
#pragma unroll
                    for (int j = 0; j < 8; j++) acc[i][j] += a[i] * bb[j];
            }
            __syncthreads();
        }
    }

    // epilogue: bias + clipped activation
#pragma unroll
    for (int i = 0; i < 8; i++) {
        int rr = row0 + tr + i;
        if (rr >= N) continue;
        float* orow = Out + (size_t)rr * M;
#pragma unroll
        for (int j = 0; j < 8; j++) {
            int m = col0 + tc + j;
            if (m >= M) continue;
            float v = acc[i][j] + bias[m];
            v = fminf(fmaxf(v, 0.f), actmax);
            orow[m] = v;
        }
    }
}

// ---------------------------------------------------------------------------
extern "C" void kernel_launch(void* const* d_in, const int* in_sizes, int n_in,
                              void* d_out, int out_size) {
    (void)in_sizes; (void)n_in; (void)out_size;
    const float* x    = (const float*)d_in[0];
    const float* h1_w = (const float*)d_in[1];  const float* h1_b = (const float*)d_in[2];
    const float* h2_w = (const float*)d_in[3];  const float* h2_b = (const float*)d_in[4];
    const float* bn2g = (const float*)d_in[5];  const float* bn2b = (const float*)d_in[6];
    const float* h3_w = (const float*)d_in[7];  const float* h3_b = (const float*)d_in[8];
    const float* bn3g = (const float*)d_in[9];  const float* bn3b = (const float*)d_in[10];
    const float* h4_w = (const float*)d_in[11]; const float* h4_b = (const float*)d_in[12];
    const float* bn4g = (const float*)d_in[13]; const float* bn4b = (const float*)d_in[14];
    const float* h5_w = (const float*)d_in[15]; const float* h5_b = (const float*)d_in[16];
    const float* bn5g = (const float*)d_in[17]; const float* bn5b = (const float*)d_in[18];
    const float* l1_w = (const float*)d_in[19]; const float* l1_b = (const float*)d_in[20];
    const float* bn6g = (const float*)d_in[21]; const float* bn6b = (const float*)d_in[22];
    const float* l2_w = (const float*)d_in[23]; const float* l2_b = (const float*)d_in[24];
    const float* bn7g = (const float*)d_in[25]; const float* bn7b = (const float*)d_in[26];

    float *bufA, *bufB, *buf5, *wT1, *wT2, *wT3, *wT4, *wT5, *wF, *bF;
    float *sumP, *sumsqP, *alphaP, *deltaP, *pcS, *pcQ, *pool, *fc1, *fc1n, *fc2;
    cudaGetSymbolAddress((void**)&bufA,  g_bufA);
    cudaGetSymbolAddress((void**)&bufB,  g_bufB);
    cudaGetSymbolAddress((void**)&buf5,  g_buf5);
    cudaGetSymbolAddress((void**)&wT1,   g_wT1);
    cudaGetSymbolAddress((void**)&wT2,   g_wT2);
    cudaGetSymbolAddress((void**)&wT3,   g_wT3);
    cudaGetSymbolAddress((void**)&wT4,   g_wT4);
    cudaGetSymbolAddress((void**)&wT5,   g_wT5);
    cudaGetSymbolAddress((void**)&wF,    g_wF);
    cudaGetSymbolAddress((void**)&bF,    g_bF);
    cudaGetSymbolAddress((void**)&sumP,  g_sum);
    cudaGetSymbolAddress((void**)&sumsqP,g_sumsq);
    cudaGetSymbolAddress((void**)&alphaP,g_alpha);
    cudaGetSymbolAddress((void**)&deltaP,g_delta);
    cudaGetSymbolAddress((void**)&pcS,   g_pcS);
    cudaGetSymbolAddress((void**)&pcQ,   g_pcQ);
    cudaGetSymbolAddress((void**)&pool,  g_pool);
    cudaGetSymbolAddress((void**)&fc1,   g_fc1);
    cudaGetSymbolAddress((void**)&fc1n,  g_fc1n);
    cudaGetSymbolAddress((void**)&fc2,   g_fc2);

    // ---- weight permutations / transposes ----
    k_permute_w1 <<<(512*100 + 255)/256, 256>>>(h1_w, wT1);
    k_permute_w23<<<(512*1536 + 255)/256, 256>>>(h2_w, wT2);
    k_permute_w23<<<(512*1536 + 255)/256, 256>>>(h3_w, wT3);
    k_transpose  <<<(512*512 + 255)/256, 256>>>(h4_w, wT4, 512, 512);
    k_transpose  <<<(1500*512 + 255)/256, 256>>>(h5_w, wT5, 1500, 512);

    dim3 blk(256);

    // ---- stage 1: splice(0..4)+conv h1 (K=5x20), relu -> bufA [B,T1,512] ----
    {
        dim3 g((N1 + 127)/128, (512 + 127)/128);
        gemm_conv<<<g, blk>>>(x, wT1, h1_b, bufA, TT0, TT1, 20, 5, 1, 512, N1, 1e30f);
    }
    // bn1 (affine=False) stats -> fold into stage-2 weights
    k_zero<<<(1536+255)/256,256>>>(sumP, 1536);
    k_zero<<<(1536+255)/256,256>>>(sumsqP, 1536);
    { dim3 g(2, 256); k_stats<<<g, blk>>>(bufA, N1, 512, sumP, sumsqP); }
    k_bn_params<<<2, 256>>>(sumP, sumsqP, 1.f/(float)N1, nullptr, nullptr, 512, alphaP, deltaP);
    k_fold_w<<<(1536*512 + 255)/256, 256>>>(wT2, wF, alphaP, 512, 1536, 512);
    k_fold_b<<<2, 256>>>(wT2, h2_b, bF, deltaP, 512, 1536, 512);

    // ---- stage 2: splice(0,2,4)+conv h2 (K=3x512), relu -> bufB [B,T2,512] ----
    {
        dim3 g((N2 + 127)/128, 4);
        gemm_conv<<<g, blk>>>(bufA, wF, bF, bufB, TT1, TT2, 512, 3, 2, 512, N2, 1e30f);
    }
    k_zero<<<(1536+255)/256,256>>>(sumP, 1536);
    k_zero<<<(1536+255)/256,256>>>(sumsqP, 1536);
    { dim3 g(2, 256); k_stats<<<g, blk>>>(bufB, N2, 512, sumP, sumsqP); }
    k_bn_params<<<2, 256>>>(sumP, sumsqP, 1.f/(float)N2, bn2g, bn2b, 512, alphaP, deltaP);
    k_fold_w<<<(1536*512 + 255)/256, 256>>>(wT3, wF, alphaP, 512, 1536, 512);
    k_fold_b<<<2, 256>>>(wT3, h3_b, bF, deltaP, 512, 1536, 512);

    // ---- stage 3: splice(0,3,6)+conv h3, relu -> bufA [B,T3,512] ----
    {
        dim3 g((N3 + 127)/128, 4);
        gemm_conv<<<g, blk>>>(bufB, wF, bF, bufA, TT2, TT3, 512, 3, 3, 512, N3, 1e30f);
    }
    k_zero<<<(1536+255)/256,256>>>(sumP, 1536);
    k_zero<<<(1536+255)/256,256>>>(sumsqP, 1536);
    { dim3 g(2, 256); k_stats<<<g, blk>>>(bufA, N3, 512, sumP, sumsqP); }
    k_bn_params<<<2, 256>>>(sumP, sumsqP, 1.f/(float)N3, bn3g, bn3b, 512, alphaP, deltaP);
    k_fold_w<<<(512*512 + 255)/256, 256>>>(wT4, wF, alphaP, 512, 512, 512);
    k_fold_b<<<2, 256>>>(wT4, h4_b, bF, deltaP, 512, 512, 512);

    // ---- stage 4: conv h4 (512x512), relu6 -> bufB [B,T3,512] ----
    {
        dim3 g((N3 + 127)/128, 4);
        gemm_conv<<<g, blk>>>(bufA, wF, bF, bufB, TT3, TT3, 512, 1, 0, 512, N3, 6.f);
    }
    k_zero<<<(1536+255)/256,256>>>(sumP, 1536);
    k_zero<<<(1536+255)/256,256>>>(sumsqP, 1536);
    { dim3 g(2, 256); k_stats<<<g, blk>>>(bufB, N3, 512, sumP, sumsqP); }
    k_bn_params<<<2, 256>>>(sumP, sumsqP, 1.f/(float)N3, bn4g, bn4b, 512, alphaP, deltaP);
    k_fold_w<<<(512*1500 + 255)/256, 256>>>(wT5, wF, alphaP, 512, 512, 1500);
    k_fold_b<<<(1500+255)/256, 256>>>(wT5, h5_b, bF, deltaP, 512, 512, 1500);

    // ---- stage 5: conv h5 (1500x512), relu6 -> buf5 [B,T3,1500] ----
    {
        dim3 g((N3 + 127)/128, (1500 + 127)/128);
        gemm_conv<<<g, blk>>>(bufB, wF, bF, buf5, TT3, TT3, 512, 1, 0, 1500, N3, 6.f);
    }

    // ---- bn5 + stats pooling (analytic via per-(b,c) sums) ----
    k_zero<<<(BATCH*1500 + 255)/256, 256>>>(pcS, BATCH*1500);
    k_zero<<<(BATCH*1500 + 255)/256, 256>>>(pcQ, BATCH*1500);
    { dim3 g((1500 + 255)/256, BATCH, 8); k_pcstats<<<g, blk>>>(buf5, TT3, 1500, pcS, pcQ); }
    k_pool<<<(1500 + 255)/256, 256>>>(pcS, pcQ, TT3, 1500, bn5g, bn5b, pool);

    // ---- FC head ----
    k_fc <<<512, 128>>>(pool, l1_w, l1_b, fc1, 3000, 512);
    k_bnc<<<2, 256>>>(fc1, bn6g, bn6b, fc1n, 512);
    k_fc <<<512, 128>>>(fc1n, l2_w, l2_b, fc2, 512, 512);
    k_bnc<<<2, 256>>>(fc2, bn7g, bn7b, (float*)d_out, 512);
}

// round 3
// speedup vs baseline: 1.0021x; 1.0021x over previous
#include <cuda_runtime.h>
#include <cuda_bf16.h>
#include <math.h>

// ---------------------------------------------------------------------------
// TDNN (x-vector) forward.
// Layout convention: activations stored [B, T, C] row-major (C contiguous).
// Splice(offsets) + conv1x1 == GEMM with permuted weights reading time-shifted
// contiguous rows. BatchNorm folded into the NEXT layer's weights.
// ---------------------------------------------------------------------------

#define BATCH 32
#define TT0 2048
#define TT1 2044   // after splice (0,1,2,3,4)
#define TT2 2040   // after splice (0,2,4)
#define TT3 2034   // after splice (0,3,6)

#define N1 (BATCH*TT1)   // 65408
#define N2 (BATCH*TT2)   // 65280
#define N3 (BATCH*TT3)   // 65088

// ------------------------- scratch (static device memory) ------------------
__device__ float g_bufA[(size_t)BATCH * TT1 * 512];   // 134 MB
__device__ float g_bufB[(size_t)BATCH * TT1 * 512];   // 134 MB
__device__ float g_buf5[(size_t)BATCH * TT3 * 1500];  // 390 MB

__device__ float g_wT1[100 * 512];
__device__ float g_wT2[1536 * 512];
__device__ float g_wT3[1536 * 512];
__device__ float g_wT4[512 * 512];
__device__ float g_wT5[512 * 1500];
__device__ float g_wF [1536 * 512];     // folded weights (reused per stage; >= 512*1500)
__device__ float g_bF [1500];           // folded bias

__device__ float g_sum  [1536];
__device__ float g_sumsq[1536];
__device__ float g_alpha[512];
__device__ float g_delta[512];

__device__ float g_pcS [BATCH * 1500];
__device__ float g_pcQ [BATCH * 1500];
__device__ float g_pool[BATCH * 3000];
__device__ float g_fc1 [BATCH * 512];
__device__ float g_fc1n[BATCH * 512];
__device__ float g_fc2 [BATCH * 512];

// ------------------------- tiny utility kernels ----------------------------
__global__ void k_zero(float* p, int n) {
    int i = blockIdx.x * blockDim.x + threadIdx.x;
    if (i < n) p[i] = 0.f;
}

// h1_w [512,100], k = f*5+c  ->  wT[(c*20+f)*512 + m]
__global__ void k_permute_w1(const float* __restrict__ w, float* __restrict__ wT) {
    int i = blockIdx.x * blockDim.x + threadIdx.x;
    if (i >= 512 * 100) return;
    int m = i / 100, k = i % 100;
    int f = k / 5, c = k % 5;
    wT[(c * 20 + f) * 512 + m] = w[i];
}

// h{2,3}_w [512,1536], k = f*3+c  ->  wT[(c*512+f)*512 + m]
__global__ void k_permute_w23(const float* __restrict__ w, float* __restrict__ wT) {
    int i = blockIdx.x * blockDim.x + threadIdx.x;
    if (i >= 512 * 1536) return;
    int m = i / 1536, k = i % 1536;
    int f = k / 3, c = k % 3;
    wT[(c * 512 + f) * 512 + m] = w[i];
}

// generic transpose w [M,K] -> wT [K,M]
__global__ void k_transpose(const float* __restrict__ w, float* __restrict__ wT, int M, int K) {
    int i = blockIdx.x * blockDim.x + threadIdx.x;
    if (i >= M * K) return;
    int m = i / K, k = i % K;
    wT[k * M + m] = w[i];
}

// per-channel BN params from raw sums: alpha = rsqrt(var+eps)*gamma,
// delta = beta - mean*alpha
__global__ void k_bn_params(const float* __restrict__ sum, const float* __restrict__ sumsq,
                            float invN, const float* __restrict__ gamma,
                            const float* __restrict__ beta, int F,
                            float* __restrict__ alpha, float* __restrict__ delta) {
    int f = blockIdx.x * blockDim.x + threadIdx.x;
    if (f >= F) return;
    float mean = sum[f] * invN;
    float var  = sumsq[f] * invN - mean * mean;
    float s    = rsqrtf(var + 1e-5f);
    float g = gamma ? gamma[f] : 1.f;
    float b = beta  ? beta[f]  : 0.f;
    float a = s * g;
    alpha[f] = a;
    delta[f] = b - mean * a;
}

// wF[k*M+m] = wT[k*M+m] * alpha[k % F]
__global__ void k_fold_w(const float* __restrict__ wT, float* __restrict__ wF,
                         const float* __restrict__ alpha, int F, int K, int M) {
    int i = blockIdx.x * blockDim.x + threadIdx.x;
    if (i >= K * M) return;
    int k = i / M;
    wF[i] = wT[i] * alpha[k % F];
}

// bF[m] = bias[m] + sum_k wT[k*M+m] * delta[k % F]
__global__ void k_fold_b(const float* __restrict__ wT, const float* __restrict__ bias,
                         float* __restrict__ bF, const float* __restrict__ delta,
                         int F, int K, int M) {
    int m = blockIdx.x * blockDim.x + threadIdx.x;
    if (m >= M) return;
    float acc = bias[m];
    for (int k = 0; k < K; k++)
        acc += wT[k * M + m] * delta[k % F];
    bF[m] = acc;
}

// per-channel sum/sumsq over [N, M]
__global__ void k_stats(const float* __restrict__ X, int N, int M,
                        float* __restrict__ sum, float* __restrict__ sumsq) {
    int c = blockIdx.x * blockDim.x + threadIdx.x;
    if (c >= M) return;
    int rows_per = (N + gridDim.y - 1) / gridDim.y;
    int r0 = blockIdx.y * rows_per;
    int r1 = min(N, r0 + rows_per);
    float s = 0.f, q = 0.f;
    for (int r = r0; r < r1; r++) {
        float v = X[(size_t)r * M + c];
        s += v; q += v * v;
    }
    atomicAdd(&sum[c], s);
    atomicAdd(&sumsq[c], q);
}

// per-(b,c) sum/sumsq over time for stage-5 output [B, T, M]
__global__ void k_pcstats(const float* __restrict__ X, int T, int M,
                          float* __restrict__ pcS, float* __restrict__ pcQ) {
    int c = blockIdx.x * blockDim.x + threadIdx.x;
    if (c >= M) return;
    int b = blockIdx.y;
    int tper = (T + gridDim.z - 1) / gridDim.z;
    int t0 = blockIdx.z * tper;
    int t1 = min(T, t0 + tper);
    float s = 0.f, q = 0.f;
    for (int t = t0; t < t1; t++) {
        float v = X[((size_t)(b * T + t)) * M + c];
        s += v; q += v * v;
    }
    atomicAdd(&pcS[b * M + c], s);
    atomicAdd(&pcQ[b * M + c], q);
}

// bn5 + stats pooling, fully analytic from per-(b,c) sums
__global__ void k_pool(const float* __restrict__ pcS, const float* __restrict__ pcQ,
                       int T, int M, const float* __restrict__ gamma,
                       const float* __restrict__ beta, float* __restrict__ pooled) {
    int c = blockIdx.x * blockDim.x + threadIdx.x;
    if (c >= M) return;
    float gs = 0.f, gq = 0.f;
    for (int b = 0; b < BATCH; b++) { gs += pcS[b * M + c]; gq += pcQ[b * M + c]; }
    float Nf = (float)(BATCH * T);
    float mean = gs / Nf;
    float var  = gq / Nf - mean * mean;
    float s    = rsqrtf(var + 1e-5f);
    float a    = s * gamma[c];
    float bt   = beta[c];
    float Tf   = (float)T;
    for (int b = 0; b < BATCH; b++) {
        float S1 = pcS[b * M + c], S2 = pcQ[b * M + c];
        float mt = S1 / Tf;
        float vt = (S2 - S1 * S1 / Tf) / (Tf - 1.f);       // unbiased (torch.std)
        pooled[b * 2 * M + c]     = (mt - mean) * a + bt;
        pooled[b * 2 * M + M + c] = sqrtf(fmaxf(vt, 0.f)) * fabsf(a);
    }
}

// small FC: Y[b,m] = relu6( X[b,:] . W[m,:] + bias[m] ), one block per m
__global__ void k_fc(const float* __restrict__ X, const float* __restrict__ W,
                     const float* __restrict__ bias, float* __restrict__ Y,
                     int K, int M) {
    __shared__ float red[4][32];
    int m = blockIdx.x;
    int tid = threadIdx.x;
    float acc[BATCH];
#pragma unroll
    for (int b = 0; b < BATCH; b++) acc[b] = 0.f;
    for (int k = tid; k < K; k += blockDim.x) {
        float w = W[m * K + k];
#pragma unroll
        for (int b = 0; b < BATCH; b++) acc[b] += X[b * K + k] * w;
    }
#pragma unroll
    for (int b = 0; b < BATCH; b++) {
        float v = acc[b];
#pragma unroll
        for (int o = 16; o; o >>= 1) v += __shfl_down_sync(0xffffffffu, v, o);
        if ((tid & 31) == 0) red[tid >> 5][b] = v;
    }
    __syncthreads();
    if (tid < BATCH) {
        float v = red[0][tid] + red[1][tid] + red[2][tid] + red[3][tid];
        v += bias[m];
        v = fminf(fmaxf(v, 0.f), 6.f);
        Y[tid * M + m] = v;
    }
}

// BatchNorm over batch dim on [B, M] (biased var)
__global__ void k_bnc(const float* __restrict__ X, const float* __restrict__ gamma,
                      const float* __restrict__ beta, float* __restrict__ Y, int M) {
    int j = blockIdx.x * blockDim.x + threadIdx.x;
    if (j >= M) return;
    float s = 0.f, q = 0.f;
    for (int b = 0; b < BATCH; b++) { float v = X[b * M + j]; s += v; q += v * v; }
    float mean = s / (float)BATCH;
    float var  = q / (float)BATCH - mean * mean;
    float sc   = rsqrtf(var + 1e-5f) * gamma[j];
    for (int b = 0; b < BATCH; b++)
        Y[b * M + j] = (X[b * M + j] - mean) * sc + beta[j];
}

// ------------------------- main GEMM (splice-aware conv1x1) -----------------
// Out[r, m] = act( sum_c sum_f W[(c*F+f)*M + m] * In[(b*Tin + t + c*step)*F + f] + bias[m] )
// r = b*Tout + t, r < N.  Tile 128x128, BK=16, 256 threads, 8x8 per thread.
__global__ __launch_bounds__(256, 2)
void gemm_conv(const float* __restrict__ In, const float* __restrict__ W,
               const float* __restrict__ bias, float* __restrict__ Out,
               int Tin, int Tout, int F, int NC, int step,
               int M, int N, float actmax) {
    __shared__ float As[16][128];
    __shared__ float Bs[16][128];

    const int tid  = threadIdx.x;
    const int row0 = blockIdx.x * 128;
    const int col0 = blockIdx.y * 128;

    // A-load mapping: row = tid>>1 (0..127), k-half = (tid&1)*8
    const int arow = tid >> 1;
    const int ak0  = (tid & 1) * 8;
    const int r    = row0 + arow;
    const bool rvalid = (r < N);
    int b = 0, t = 0;
    if (rvalid) { b = r / Tout; t = r - b * Tout; }
    const float* rowBase = In + (size_t)(b * Tin + t) * F;

    // B-load mapping: k = tid>>4 (0..15), m-group = (tid&15)*8
    const int bk  = tid >> 4;
    const int bm0 = (tid & 15) * 8;

    // compute fragment coords
    const int tr = (tid >> 4) * 8;
    const int tc = (tid & 15) * 8;

    float acc[8][8];
#pragma unroll
    for (int i = 0; i < 8; i++)
#pragma unroll
        for (int j = 0; j < 8; j++) acc[i][j] = 0.f;

    for (int c = 0; c < NC; c++) {
        const float* Abase = rowBase + (size_t)(c * step) * F;
        const int kcbase = c * F;
        for (int k0 = 0; k0 < F; k0 += 16) {
            // stage A tile (transposed: As[k][row])
#pragma unroll
            for (int i = 0; i < 8; i++) {
                int kk = k0 + ak0 + i;
                float v = 0.f;
                if (rvalid && kk < F) v = Abase[kk];
                As[ak0 + i][arow] = v;
            }
            // stage B tile
            {
                int kk = k0 + bk;
                const float* wrow = W + (size_t)(kcbase + kk) * M;
#pragma unroll
                for (int j = 0; j < 8; j++) {
                    int m = col0 + bm0 + j;
                    float v = 0.f;
                    if (kk < F && m < M) v = wrow[m];
                    Bs[bk][bm0 + j] = v;
                }
            }
            __syncthreads();
#pragma unroll
            for (int kk = 0; kk < 16; kk++) {
                float a[8], bb[8];
#pragma unroll
                for (int i = 0; i < 8; i++) a[i] = As[kk][tr + i];
#pragma unroll
                for (int j = 0; j < 8; j++) bb[j] = Bs[kk][tc + j];
#pragma unroll
                for (int i = 0; i < 8; i++)
#pragma unroll
                    for (int j = 0; j < 8; j++) acc[i][j] += a[i] * bb[j];
            }
            __syncthreads();
        }
    }

    // epilogue: bias + clipped activation
#pragma unroll
    for (int i = 0; i < 8; i++) {
        int rr = row0 + tr + i;
        if (rr >= N) continue;
        float* orow = Out + (size_t)rr * M;
#pragma unroll
        for (int j = 0; j < 8; j++) {
            int m = col0 + tc + j;
            if (m >= M) continue;
            float v = acc[i][j] + bias[m];
            v = fminf(fmaxf(v, 0.f), actmax);
            orow[m] = v;
        }
    }
}

// ---------------------------------------------------------------------------
extern "C" void kernel_launch(void* const* d_in, const int* in_sizes, int n_in,
                              void* d_out, int out_size) {
    (void)in_sizes; (void)n_in; (void)out_size;
    const float* x    = (const float*)d_in[0];
    const float* h1_w = (const float*)d_in[1];  const float* h1_b = (const float*)d_in[2];
    const float* h2_w = (const float*)d_in[3];  const float* h2_b = (const float*)d_in[4];
    const float* bn2g = (const float*)d_in[5];  const float* bn2b = (const float*)d_in[6];
    const float* h3_w = (const float*)d_in[7];  const float* h3_b = (const float*)d_in[8];
    const float* bn3g = (const float*)d_in[9];  const float* bn3b = (const float*)d_in[10];
    const float* h4_w = (const float*)d_in[11]; const float* h4_b = (const float*)d_in[12];
    const float* bn4g = (const float*)d_in[13]; const float* bn4b = (const float*)d_in[14];
    const float* h5_w = (const float*)d_in[15]; const float* h5_b = (const float*)d_in[16];
    const float* bn5g = (const float*)d_in[17]; const float* bn5b = (const float*)d_in[18];
    const float* l1_w = (const float*)d_in[19]; const float* l1_b = (const float*)d_in[20];
    const float* bn6g = (const float*)d_in[21]; const float* bn6b = (const float*)d_in[22];
    const float* l2_w = (const float*)d_in[23]; const float* l2_b = (const float*)d_in[24];
    const float* bn7g = (const float*)d_in[25]; const float* bn7b = (const float*)d_in[26];

    float *bufA, *bufB, *buf5, *wT1, *wT2, *wT3, *wT4, *wT5, *wF, *bF;
    float *sumP, *sumsqP, *alphaP, *deltaP, *pcS, *pcQ, *pool, *fc1, *fc1n, *fc2;
    cudaGetSymbolAddress((void**)&bufA,  g_bufA);
    cudaGetSymbolAddress((void**)&bufB,  g_bufB);
    cudaGetSymbolAddress((void**)&buf5,  g_buf5);
    cudaGetSymbolAddress((void**)&wT1,   g_wT1);
    cudaGetSymbolAddress((void**)&wT2,   g_wT2);
    cudaGetSymbolAddress((void**)&wT3,   g_wT3);
    cudaGetSymbolAddress((void**)&wT4,   g_wT4);
    cudaGetSymbolAddress((void**)&wT5,   g_wT5);
    cudaGetSymbolAddress((void**)&wF,    g_wF);
    cudaGetSymbolAddress((void**)&bF,    g_bF);
    cudaGetSymbolAddress((void**)&sumP,  g_sum);
    cudaGetSymbolAddress((void**)&sumsqP,g_sumsq);
    cudaGetSymbolAddress((void**)&alphaP,g_alpha);
    cudaGetSymbolAddress((void**)&deltaP,g_delta);
    cudaGetSymbolAddress((void**)&pcS,   g_pcS);
    cudaGetSymbolAddress((void**)&pcQ,   g_pcQ);
    cudaGetSymbolAddress((void**)&pool,  g_pool);
    cudaGetSymbolAddress((void**)&fc1,   g_fc1);
    cudaGetSymbolAddress((void**)&fc1n,  g_fc1n);
    cudaGetSymbolAddress((void**)&fc2,   g_fc2);

    // ---- weight permutations / transposes ----
    k_permute_w1 <<<(512*100 + 255)/256, 256>>>(h1_w, wT1);
    k_permute_w23<<<(512*1536 + 255)/256, 256>>>(h2_w, wT2);
    k_permute_w23<<<(512*1536 + 255)/256, 256>>>(h3_w, wT3);
    k_transpose  <<<(512*512 + 255)/256, 256>>>(h4_w, wT4, 512, 512);
    k_transpose  <<<(1500*512 + 255)/256, 256>>>(h5_w, wT5, 1500, 512);

    dim3 blk(256);

    // ---- stage 1: splice(0..4)+conv h1 (K=5x20), relu -> bufA [B,T1,512] ----
    {
        dim3 g((N1 + 127)/128, (512 + 127)/128);
        gemm_conv<<<g, blk>>>(x, wT1, h1_b, bufA, TT0, TT1, 20, 5, 1, 512, N1, 1e30f);
    }
    // bn1 (affine=False) stats -> fold into stage-2 weights
    k_zero<<<(1536+255)/256,256>>>(sumP, 1536);
    k_zero<<<(1536+255)/256,256>>>(sumsqP, 1536);
    { dim3 g(2, 256); k_stats<<<g, blk>>>(bufA, N1, 512, sumP, sumsqP); }
    k_bn_params<<<2, 256>>>(sumP, sumsqP, 1.f/(float)N1, nullptr, nullptr, 512, alphaP, deltaP);
    k_fold_w<<<(1536*512 + 255)/256, 256>>>(wT2, wF, alphaP, 512, 1536, 512);
    k_fold_b<<<2, 256>>>(wT2, h2_b, bF, deltaP, 512, 1536, 512);

    // ---- stage 2: splice(0,2,4)+conv h2 (K=3x512), relu -> bufB [B,T2,512] ----
    {
        dim3 g((N2 + 127)/128, 4);
        gemm_conv<<<g, blk>>>(bufA, wF, bF, bufB, TT1, TT2, 512, 3, 2, 512, N2, 1e30f);
    }
    k_zero<<<(1536+255)/256,256>>>(sumP, 1536);
    k_zero<<<(1536+255)/256,256>>>(sumsqP, 1536);
    { dim3 g(2, 256); k_stats<<<g, blk>>>(bufB, N2, 512, sumP, sumsqP); }
    k_bn_params<<<2, 256>>>(sumP, sumsqP, 1.f/(float)N2, bn2g, bn2b, 512, alphaP, deltaP);
    k_fold_w<<<(1536*512 + 255)/256, 256>>>(wT3, wF, alphaP, 512, 1536, 512);
    k_fold_b<<<2, 256>>>(wT3, h3_b, bF, deltaP, 512, 1536, 512);

    // ---- stage 3: splice(0,3,6)+conv h3, relu -> bufA [B,T3,512] ----
    {
        dim3 g((N3 + 127)/128, 4);
        gemm_conv<<<g, blk>>>(bufB, wF, bF, bufA, TT2, TT3, 512, 3, 3, 512, N3, 1e30f);
    }
    k_zero<<<(1536+255)/256,256>>>(sumP, 1536);
    k_zero<<<(1536+255)/256,256>>>(sumsqP, 1536);
    { dim3 g(2, 256); k_stats<<<g, blk>>>(bufA, N3, 512, sumP, sumsqP); }
    k_bn_params<<<2, 256>>>(sumP, sumsqP, 1.f/(float)N3, bn3g, bn3b, 512, alphaP, deltaP);
    k_fold_w<<<(512*512 + 255)/256, 256>>>(wT4, wF, alphaP, 512, 512, 512);
    k_fold_b<<<2, 256>>>(wT4, h4_b, bF, deltaP, 512, 512, 512);

    // ---- stage 4: conv h4 (512x512), relu6 -> bufB [B,T3,512] ----
    {
        dim3 g((N3 + 127)/128, 4);
        gemm_conv<<<g, blk>>>(bufA, wF, bF, bufB, TT3, TT3, 512, 1, 0, 512, N3, 6.f);
    }
    k_zero<<<(1536+255)/256,256>>>(sumP, 1536);
    k_zero<<<(1536+255)/256,256>>>(sumsqP, 1536);
    { dim3 g(2, 256); k_stats<<<g, blk>>>(bufB, N3, 512, sumP, sumsqP); }
    k_bn_params<<<2, 256>>>(sumP, sumsqP, 1.f/(float)N3, bn4g, bn4b, 512, alphaP, deltaP);
    k_fold_w<<<(512*1500 + 255)/256, 256>>>(wT5, wF, alphaP, 512, 512, 1500);
    k_fold_b<<<(1500+255)/256, 256>>>(wT5, h5_b, bF, deltaP, 512, 512, 1500);

    // ---- stage 5: conv h5 (1500x512), relu6 -> buf5 [B,T3,1500] ----
    {
        dim3 g((N3 + 127)/128, (1500 + 127)/128);
        gemm_conv<<<g, blk>>>(bufB, wF, bF, buf5, TT3, TT3, 512, 1, 0, 1500, N3, 6.f);
    }

    // ---- bn5 + stats pooling (analytic via per-(b,c) sums) ----
    k_zero<<<(BATCH*1500 + 255)/256, 256>>>(pcS, BATCH*1500);
    k_zero<<<(BATCH*1500 + 255)/256, 256>>>(pcQ, BATCH*1500);
    { dim3 g((1500 + 255)/256, BATCH, 8); k_pcstats<<<g, blk>>>(buf5, TT3, 1500, pcS, pcQ); }
    k_pool<<<(1500 + 255)/256, 256>>>(pcS, pcQ, TT3, 1500, bn5g, bn5b, pool);

    // ---- FC head ----
    k_fc <<<512, 128>>>(pool, l1_w, l1_b, fc1, 3000, 512);
    k_bnc<<<2, 256>>>(fc1, bn6g, bn6b, fc1n, 512);
    k_fc <<<512, 128>>>(fc1n, l2_w, l2_b, fc2, 512, 512);
    k_bnc<<<2, 256>>>(fc2, bn7g, bn7b, (float*)d_out, 512);
}

// round 8
// speedup vs baseline: 4.3350x; 4.3260x over previous
#include <cuda_runtime.h>
#include <cuda_bf16.h>
#include <math.h>
#include <stdint.h>

#define BATCH 32
#define TT0 2048
#define TT1 2044
#define TT2 2040
#define TT3 2034
#define N1 (BATCH*TT1)
#define N2 (BATCH*TT2)
#define N3 (BATCH*TT3)

// ---------------- scratch ----------------
__device__ __nv_bfloat16 g_xsh[(size_t)N1 * 128], g_xsl[(size_t)N1 * 128];
__device__ __nv_bfloat16 g_aH0[(size_t)N1 * 512], g_aL0[(size_t)N1 * 512];
__device__ __nv_bfloat16 g_aH1[(size_t)N1 * 512], g_aL1[(size_t)N1 * 512];
__device__ __nv_bfloat16 g_5h[(size_t)N3 * 1500], g_5l[(size_t)N3 * 1500];
__device__ __nv_bfloat16 g_w1h[512 * 128], g_w1l[512 * 128];
__device__ __nv_bfloat16 g_wfh[512 * 1536], g_wfl[512 * 1536];
__device__ float g_wp2[512 * 1536], g_wp3[512 * 1536];
__device__ float g_bF[1500];
__device__ float g_sum[512], g_sumsq[512], g_alpha[512], g_delta[512];
__device__ float g_pcS[BATCH * 1500], g_pcQ[BATCH * 1500];
__device__ float g_pool[BATCH * 3000];
__device__ float g_fc1[BATCH * 512], g_fc1n[BATCH * 512], g_fc2[BATCH * 512];

// ---------------- prep / scalar kernels ----------------
__global__ void k_zero(float* p, int n) {
    int i = blockIdx.x * blockDim.x + threadIdx.x;
    if (i < n) p[i] = 0.f;
}
__device__ __forceinline__ void split_st(float v, __nv_bfloat16* ph, __nv_bfloat16* pl) {
    __nv_bfloat16 h = __float2bfloat16(v);
    *ph = h;
    *pl = __float2bfloat16(v - __bfloat162float(h));
}
__global__ void k_presplice(const float* __restrict__ x, __nv_bfloat16* __restrict__ xh,
                            __nv_bfloat16* __restrict__ xl) {
    int i = blockIdx.x * blockDim.x + threadIdx.x;
    if (i >= N1 * 128) return;
    int r = i >> 7, kk = i & 127;
    float v = 0.f;
    if (kk < 100) {
        int c = kk / 20, f = kk - c * 20;
        int b = r / TT1, t = r - b * TT1;
        v = x[((size_t)(b * TT0 + t + c)) * 20 + f];
    }
    split_st(v, &xh[i], &xl[i]);
}
__global__ void k_prepw1(const float* __restrict__ w, __nv_bfloat16* __restrict__ wh,
                         __nv_bfloat16* __restrict__ wl) {
    int i = blockIdx.x * blockDim.x + threadIdx.x;
    if (i >= 512 * 128) return;
    int m = i >> 7, kk = i & 127;
    float v = 0.f;
    if (kk < 100) {
        int c = kk / 20, f = kk - c * 20;
        v = w[m * 100 + f * 5 + c];
    }
    split_st(v, &wh[i], &wl[i]);
}
__global__ void k_permMK(const float* __restrict__ w, float* __restrict__ wP) {
    int i = blockIdx.x * blockDim.x + threadIdx.x;
    if (i >= 512 * 1536) return;
    int m = i / 1536, kp = i - m * 1536;
    int c = kp >> 9, f = kp & 511;
    wP[i] = w[m * 1536 + f * 3 + c];
}
__global__ void k_bn_params(const float* __restrict__ sum, const float* __restrict__ sumsq,
                            float invN, const float* __restrict__ gamma,
                            const float* __restrict__ beta, int F,
                            float* __restrict__ alpha, float* __restrict__ delta) {
    int f = blockIdx.x * blockDim.x + threadIdx.x;
    if (f >= F) return;
    float mean = sum[f] * invN;
    float var = sumsq[f] * invN - mean * mean;
    float a = rsqrtf(var + 1e-5f) * (gamma ? gamma[f] : 1.f);
    alpha[f] = a;
    delta[f] = (beta ? beta[f] : 0.f) - mean * a;
}
__global__ void k_fold_split(const float* __restrict__ wP, const float* __restrict__ alpha,
                             int F, int K, int MK, __nv_bfloat16* __restrict__ wh,
                             __nv_bfloat16* __restrict__ wl) {
    int i = blockIdx.x * blockDim.x + threadIdx.x;
    if (i >= MK) return;
    int k = i % K;
    split_st(wP[i] * alpha[k % F], &wh[i], &wl[i]);
}
__global__ void k_fold_bias(const float* __restrict__ wP, const float* __restrict__ b0,
                            const float* __restrict__ delta, int F, int K, int M,
                            float* __restrict__ bF) {
    int m = blockIdx.x * blockDim.x + threadIdx.x;
    if (m >= M) return;
    float acc = b0[m];
    for (int k = 0; k < K; k++) acc += wP[(size_t)m * K + k] * delta[k % F];
    bF[m] = acc;
}
__global__ void k_stats_hl(const __nv_bfloat16* __restrict__ Xh, const __nv_bfloat16* __restrict__ Xl,
                           int N, int M, float* __restrict__ sum, float* __restrict__ sumsq) {
    int c = blockIdx.x * blockDim.x + threadIdx.x;
    if (c >= M) return;
    int per = (N + gridDim.y - 1) / gridDim.y;
    int r0 = blockIdx.y * per, r1 = min(N, r0 + per);
    float s = 0.f, q = 0.f;
    for (int r = r0; r < r1; r++) {
        size_t idx = (size_t)r * M + c;
        float v = __bfloat162float(Xh[idx]) + __bfloat162float(Xl[idx]);
        s += v; q += v * v;
    }
    atomicAdd(&sum[c], s);
    atomicAdd(&sumsq[c], q);
}
__global__ void k_pcstats_hl(const __nv_bfloat16* __restrict__ Xh, const __nv_bfloat16* __restrict__ Xl,
                             int T, int M, float* __restrict__ pcS, float* __restrict__ pcQ) {
    int c = blockIdx.x * blockDim.x + threadIdx.x;
    if (c >= M) return;
    int b = blockIdx.y;
    int per = (T + gridDim.z - 1) / gridDim.z;
    int t0 = blockIdx.z * per, t1 = min(T, t0 + per);
    float s = 0.f, q = 0.f;
    for (int t = t0; t < t1; t++) {
        size_t idx = ((size_t)(b * T + t)) * M + c;
        float v = __bfloat162float(Xh[idx]) + __bfloat162float(Xl[idx]);
        s += v; q += v * v;
    }
    atomicAdd(&pcS[b * M + c], s);
    atomicAdd(&pcQ[b * M + c], q);
}
__global__ void k_pool(const float* __restrict__ pcS, const float* __restrict__ pcQ,
                       int T, int M, const float* __restrict__ gamma,
                       const float* __restrict__ beta, float* __restrict__ pooled) {
    int c = blockIdx.x * blockDim.x + threadIdx.x;
    if (c >= M) return;
    float gs = 0.f, gq = 0.f;
    for (int b = 0; b < BATCH; b++) { gs += pcS[b * M + c]; gq += pcQ[b * M + c]; }
    float Nf = (float)(BATCH * T);
    float mean = gs / Nf;
    float var = gq / Nf - mean * mean;
    float a = rsqrtf(var + 1e-5f) * gamma[c];
    float bt = beta[c];
    float Tf = (float)T;
    for (int b = 0; b < BATCH; b++) {
        float S1 = pcS[b * M + c], S2 = pcQ[b * M + c];
        float mt = S1 / Tf;
        float vt = (S2 - S1 * S1 / Tf) / (Tf - 1.f);
        pooled[b * 2 * M + c] = (mt - mean) * a + bt;
        pooled[b * 2 * M + M + c] = sqrtf(fmaxf(vt, 0.f)) * fabsf(a);
    }
}
__global__ void k_fc(const float* __restrict__ X, const float* __restrict__ W,
                     const float* __restrict__ bias, float* __restrict__ Y, int K, int M) {
    __shared__ float red[4][32];
    int m = blockIdx.x, tid = threadIdx.x;
    float acc[BATCH];
#pragma unroll
    for (int b = 0; b < BATCH; b++) acc[b] = 0.f;
    for (int k = tid; k < K; k += blockDim.x) {
        float w = W[(size_t)m * K + k];
#pragma unroll
        for (int b = 0; b < BATCH; b++) acc[b] += X[b * K + k] * w;
    }
#pragma unroll
    for (int b = 0; b < BATCH; b++) {
        float v = acc[b];
#pragma unroll
        for (int o = 16; o; o >>= 1) v += __shfl_down_sync(0xffffffffu, v, o);
        if ((tid & 31) == 0) red[tid >> 5][b] = v;
    }
    __syncthreads();
    if (tid < BATCH) {
        float v = red[0][tid] + red[1][tid] + red[2][tid] + red[3][tid] + bias[m];
        Y[tid * M + m] = fminf(fmaxf(v, 0.f), 6.f);
    }
}
__global__ void k_bnc(const float* __restrict__ X, const float* __restrict__ gamma,
                      const float* __restrict__ beta, float* __restrict__ Y, int M) {
    int j = blockIdx.x * blockDim.x + threadIdx.x;
    if (j >= M) return;
    float s = 0.f, q = 0.f;
    for (int b = 0; b < BATCH; b++) { float v = X[b * M + j]; s += v; q += v * v; }
    float mean = s / (float)BATCH;
    float var = q / (float)BATCH - mean * mean;
    float sc = rsqrtf(var + 1e-5f) * gamma[j];
    for (int b = 0; b < BATCH; b++) Y[b * M + j] = (X[b * M + j] - mean) * sc + beta[j];
}

// ---------------- HMMA GEMM (mma.sync m16n8k16 bf16, hi/lo 3-product) -------
// C[128 rows x 128 cols] per CTA. BK=32, double-buffered cp.async.
// SMEM buffer layout (per 32KB stage): Ah@0, Al@8192, Wh@16384, Wl@24576.
// Row stride 64B; 16B-slot swizzle: slot' = kg ^ ((row>>1)&3).
__device__ __forceinline__ uint32_t smem_u32(const void* p) {
    uint32_t a;
    asm("{ .reg .u64 t; cvta.to.shared.u64 t, %1; cvt.u32.u64 %0, t; }" : "=r"(a) : "l"(p));
    return a;
}
__device__ __forceinline__ void cpa(uint32_t dst, const void* src, uint32_t n) {
    asm volatile("cp.async.cg.shared.global [%0], [%1], 16, %2;" :: "r"(dst), "l"(src), "r"(n) : "memory");
}
#define LDM4(v, a) \
    asm volatile("ldmatrix.sync.aligned.m8n8.x4.shared.b16 {%0,%1,%2,%3}, [%4];" \
        : "=r"((v)[0]), "=r"((v)[1]), "=r"((v)[2]), "=r"((v)[3]) : "r"(a))
#define MMA(d, a, b0, b1) \
    asm volatile("mma.sync.aligned.m16n8k16.row.col.f32.bf16.bf16.f32 " \
        "{%0,%1,%2,%3}, {%4,%5,%6,%7}, {%8,%9}, {%0,%1,%2,%3};" \
        : "+f"((d)[0]), "+f"((d)[1]), "+f"((d)[2]), "+f"((d)[3]) \
        : "r"((a)[0]), "r"((a)[1]), "r"((a)[2]), "r"((a)[3]), "r"(b0), "r"(b1))

__global__ __launch_bounds__(256)
void mma_gemm(const __nv_bfloat16* __restrict__ inH, const __nv_bfloat16* __restrict__ inL,
              const __nv_bfloat16* __restrict__ wH, const __nv_bfloat16* __restrict__ wL,
              const float* __restrict__ bias,
              __nv_bfloat16* __restrict__ outH, __nv_bfloat16* __restrict__ outL,
              int Tin, int Tout, int F, int step,
              int Ktot, int Mtot, int Mstride, int Nrows, float actmax) {
    extern __shared__ char smem[];
    const uint32_t sb = smem_u32(smem);
    const int t = threadIdx.x;
    const int row0 = blockIdx.x * 128;
    const int colbase = blockIdx.y * 128;
    const int NKC = Ktot >> 5, FC = F >> 5;

    // ---- loader mapping: rows lr, lr+64; 16B slot kg ----
    const int lr = t >> 2, kg = t & 3;
    int ra = row0 + lr, rb = row0 + lr + 64;
    bool va = ra < Nrows, vb = rb < Nrows;
    size_t aba = 0, abb = 0;
    if (va) { int b_ = ra / Tout; aba = (size_t)(b_ * Tin + (ra - b_ * Tout)) * F; }
    if (vb) { int b_ = rb / Tout; abb = (size_t)(b_ * Tin + (rb - b_ * Tout)) * F; }
    int na = colbase + lr, nb = colbase + lr + 64;
    bool wva = na < Mtot, wvb = nb < Mtot;
    size_t wba = wva ? (size_t)na * Ktot : 0, wbb = wvb ? (size_t)nb * Ktot : 0;
    const uint32_t swz = (uint32_t)((kg ^ ((lr >> 1) & 3)) << 4);
    const uint32_t dRa = sb + lr * 64 + swz, dRb = sb + (lr + 64) * 64 + swz;
    uint32_t vA = va ? 16u : 0u, vB = vb ? 16u : 0u, vWa = wva ? 16u : 0u, vWb = wvb ? 16u : 0u;

#define LOAD_CHUNK(kc, buf) do { \
        uint32_t bo = (uint32_t)(buf) << 15; \
        int c_ = (kc) / FC; \
        size_t ao = (size_t)c_ * step * F + (size_t)((kc) - c_ * FC) * 32 + kg * 8; \
        size_t wo = (size_t)(kc) * 32 + kg * 8; \
        cpa(dRa + bo,         inH + aba + ao, vA); \
        cpa(dRb + bo,         inH + abb + ao, vB); \
        cpa(dRa + 8192 + bo,  inL + aba + ao, vA); \
        cpa(dRb + 8192 + bo,  inL + abb + ao, vB); \
        cpa(dRa + 16384 + bo, wH + wba + wo, vWa); \
        cpa(dRb + 16384 + bo, wH + wbb + wo, vWb); \
        cpa(dRa + 24576 + bo, wL + wba + wo, vWa); \
        cpa(dRb + 24576 + bo, wL + wbb + wo, vWb); \
        asm volatile("cp.async.commit_group;" ::: "memory"); \
    } while (0)

    // ---- compute mapping: warp (wr, wc2) -> rows wr*64+, cols wc2*32+ ----
    const int wid = t >> 5, lane = t & 31;
    const int wr = wid & 1, wc2 = wid >> 1;
    uint32_t aAd[4], wAd[2];
    {
        int rbase = wr * 64 + (lane & 15);
        int kg0 = lane >> 4;
#pragma unroll
        for (int mi = 0; mi < 4; mi++) {
            int rr = rbase + mi * 16;
            aAd[mi] = sb + rr * 64 + ((kg0 ^ ((rr >> 1) & 3)) << 4);
        }
        int nbase = wc2 * 32 + (lane & 7) + ((lane >> 4) << 3);
        int kgw = (lane >> 3) & 1;
#pragma unroll
        for (int cj = 0; cj < 2; cj++) {
            int nn = nbase + cj * 16;
            wAd[cj] = sb + 16384 + nn * 64 + ((kgw ^ ((nn >> 1) & 3)) << 4);
        }
    }

    float acc[4][4][4];
#pragma unroll
    for (int i = 0; i < 4; i++)
#pragma unroll
        for (int j = 0; j < 4; j++)
#pragma unroll
            for (int q = 0; q < 4; q++) acc[i][j][q] = 0.f;

    LOAD_CHUNK(0, 0);
    for (int kc = 0; kc < NKC; kc++) {
        asm volatile("cp.async.wait_group 0;" ::: "memory");
        __syncthreads();
        if (kc + 1 < NKC) LOAD_CHUNK(kc + 1, (kc + 1) & 1);
        uint32_t bo = (uint32_t)(kc & 1) << 15;
#pragma unroll
        for (int ks = 0; ks < 2; ks++) {
            uint32_t kx = (uint32_t)ks << 5;
            uint32_t ah[4][4], al[4][4], wh[2][4], wl[2][4];
#pragma unroll
            for (int mi = 0; mi < 4; mi++) {
                uint32_t ad = (aAd[mi] ^ kx) + bo;
                LDM4(ah[mi], ad);
                LDM4(al[mi], ad + 8192);
            }
#pragma unroll
            for (int cj = 0; cj < 2; cj++) {
                uint32_t ad = (wAd[cj] ^ kx) + bo;
                LDM4(wh[cj], ad);
                LDM4(wl[cj], ad + 8192);
            }
#pragma unroll
            for (int mi = 0; mi < 4; mi++)
#pragma unroll
                for (int nj = 0; nj < 4; nj++) {
                    int cj = nj >> 1, h = (nj & 1) << 1;
                    MMA(acc[mi][nj], ah[mi], wh[cj][h], wh[cj][h + 1]);
                    MMA(acc[mi][nj], ah[mi], wl[cj][h], wl[cj][h + 1]);
                    MMA(acc[mi][nj], al[mi], wh[cj][h], wh[cj][h + 1]);
                }
        }
    }

    // ---- epilogue ----
    const int re = row0 + wr * 64 + (lane >> 2);
    const int ce = colbase + wc2 * 32 + ((lane & 3) << 1);
#pragma unroll
    for (int nj = 0; nj < 4; nj++) {
        int m = ce + nj * 8;
        if (m >= Mtot) continue;
        float b0 = bias[m], b1 = bias[m + 1];
#pragma unroll
        for (int mi = 0; mi < 4; mi++) {
#pragma unroll
            for (int half = 0; half < 2; half++) {
                int r = re + mi * 16 + half * 8;
                if (r >= Nrows) continue;
                float v0 = fminf(fmaxf(acc[mi][nj][half * 2] + b0, 0.f), actmax);
                float v1 = fminf(fmaxf(acc[mi][nj][half * 2 + 1] + b1, 0.f), actmax);
                __nv_bfloat16 h0 = __float2bfloat16(v0), h1 = __float2bfloat16(v1);
                __nv_bfloat16 l0 = __float2bfloat16(v0 - __bfloat162float(h0));
                __nv_bfloat16 l1 = __float2bfloat16(v1 - __bfloat162float(h1));
                size_t ob = (size_t)r * Mstride + m;
                *(__nv_bfloat162*)(outH + ob) = __halves2bfloat162(h0, h1);
                *(__nv_bfloat162*)(outL + ob) = __halves2bfloat162(l0, l1);
            }
        }
    }
#undef LOAD_CHUNK
}

// ---------------------------------------------------------------------------
extern "C" void kernel_launch(void* const* d_in, const int* in_sizes, int n_in,
                              void* d_out, int out_size) {
    (void)in_sizes; (void)n_in; (void)out_size;
    const float* x    = (const float*)d_in[0];
    const float* h1_w = (const float*)d_in[1];  const float* h1_b = (const float*)d_in[2];
    const float* h2_w = (const float*)d_in[3];  const float* h2_b = (const float*)d_in[4];
    const float* bn2g = (const float*)d_in[5];  const float* bn2b = (const float*)d_in[6];
    const float* h3_w = (const float*)d_in[7];  const float* h3_b = (const float*)d_in[8];
    const float* bn3g = (const float*)d_in[9];  const float* bn3b = (const float*)d_in[10];
    const float* h4_w = (const float*)d_in[11]; const float* h4_b = (const float*)d_in[12];
    const float* bn4g = (const float*)d_in[13]; const float* bn4b = (const float*)d_in[14];
    const float* h5_w = (const float*)d_in[15]; const float* h5_b = (const float*)d_in[16];
    const float* bn5g = (const float*)d_in[17]; const float* bn5b = (const float*)d_in[18];
    const float* l1_w = (const float*)d_in[19]; const float* l1_b = (const float*)d_in[20];
    const float* bn6g = (const float*)d_in[21]; const float* bn6b = (const float*)d_in[22];
    const float* l2_w = (const float*)d_in[23]; const float* l2_b = (const float*)d_in[24];
    const float* bn7g = (const float*)d_in[25]; const float* bn7b = (const float*)d_in[26];

    __nv_bfloat16 *xsh, *xsl, *aH0, *aL0, *aH1, *aL1, *b5h, *b5l, *w1h, *w1l, *wfh, *wfl;
    float *wp2, *wp3, *bF, *sumP, *sumsqP, *alphaP, *deltaP, *pcS, *pcQ, *pool, *fc1, *fc1n, *fc2;
    cudaGetSymbolAddress((void**)&xsh, g_xsh);   cudaGetSymbolAddress((void**)&xsl, g_xsl);
    cudaGetSymbolAddress((void**)&aH0, g_aH0);   cudaGetSymbolAddress((void**)&aL0, g_aL0);
    cudaGetSymbolAddress((void**)&aH1, g_aH1);   cudaGetSymbolAddress((void**)&aL1, g_aL1);
    cudaGetSymbolAddress((void**)&b5h, g_5h);    cudaGetSymbolAddress((void**)&b5l, g_5l);
    cudaGetSymbolAddress((void**)&w1h, g_w1h);   cudaGetSymbolAddress((void**)&w1l, g_w1l);
    cudaGetSymbolAddress((void**)&wfh, g_wfh);   cudaGetSymbolAddress((void**)&wfl, g_wfl);
    cudaGetSymbolAddress((void**)&wp2, g_wp2);   cudaGetSymbolAddress((void**)&wp3, g_wp3);
    cudaGetSymbolAddress((void**)&bF, g_bF);
    cudaGetSymbolAddress((void**)&sumP, g_sum);  cudaGetSymbolAddress((void**)&sumsqP, g_sumsq);
    cudaGetSymbolAddress((void**)&alphaP, g_alpha); cudaGetSymbolAddress((void**)&deltaP, g_delta);
    cudaGetSymbolAddress((void**)&pcS, g_pcS);   cudaGetSymbolAddress((void**)&pcQ, g_pcQ);
    cudaGetSymbolAddress((void**)&pool, g_pool);
    cudaGetSymbolAddress((void**)&fc1, g_fc1);   cudaGetSymbolAddress((void**)&fc1n, g_fc1n);
    cudaGetSymbolAddress((void**)&fc2, g_fc2);

    cudaFuncSetAttribute(mma_gemm, cudaFuncAttributeMaxDynamicSharedMemorySize, 65536);
    const float BIG = 3.0e38f;

    // prep
    k_presplice<<<(N1 * 128 + 255) / 256, 256>>>(x, xsh, xsl);
    k_prepw1<<<(512 * 128 + 255) / 256, 256>>>(h1_w, w1h, w1l);
    k_permMK<<<(512 * 1536 + 255) / 256, 256>>>(h2_w, wp2);
    k_permMK<<<(512 * 1536 + 255) / 256, 256>>>(h3_w, wp3);

    // stage 1: K=128 (padded), M=512, relu
    { dim3 g(N1 / 128, 4);
      mma_gemm<<<g, 256, 65536>>>(xsh, xsl, w1h, w1l, h1_b, aH0, aL0,
                                  TT1, TT1, 128, 0, 128, 512, 512, N1, BIG); }
    k_zero<<<2, 256>>>(sumP, 512); k_zero<<<2, 256>>>(sumsqP, 512);
    { dim3 g(2, 256); k_stats_hl<<<g, 256>>>(aH0, aL0, N1, 512, sumP, sumsqP); }
    k_bn_params<<<2, 256>>>(sumP, sumsqP, 1.f / (float)N1, nullptr, nullptr, 512, alphaP, deltaP);
    k_fold_split<<<(512 * 1536 + 255) / 256, 256>>>(wp2, alphaP, 512, 1536, 512 * 1536, wfh, wfl);
    k_fold_bias<<<2, 256>>>(wp2, h2_b, deltaP, 512, 1536, 512, bF);

    // stage 2: K=1536 (3x512, step 2), M=512, relu
    { dim3 g(N2 / 128, 4);
      mma_gemm<<<g, 256, 65536>>>(aH0, aL0, wfh, wfl, bF, aH1, aL1,
                                  TT1, TT2, 512, 2, 1536, 512, 512, N2, BIG); }
    k_zero<<<2, 256>>>(sumP, 512); k_zero<<<2, 256>>>(sumsqP, 512);
    { dim3 g(2, 256); k_stats_hl<<<g, 256>>>(aH1, aL1, N2, 512, sumP, sumsqP); }
    k_bn_params<<<2, 256>>>(sumP, sumsqP, 1.f / (float)N2, bn2g, bn2b, 512, alphaP, deltaP);
    k_fold_split<<<(512 * 1536 + 255) / 256, 256>>>(wp3, alphaP, 512, 1536, 512 * 1536, wfh, wfl);
    k_fold_bias<<<2, 256>>>(wp3, h3_b, deltaP, 512, 1536, 512, bF);

    // stage 3: K=1536 (3x512, step 3), M=512, relu
    { dim3 g((N3 + 127) / 128, 4);
      mma_gemm<<<g, 256, 65536>>>(aH1, aL1, wfh, wfl, bF, aH0, aL0,
                                  TT2, TT3, 512, 3, 1536, 512, 512, N3, BIG); }
    k_zero<<<2, 256>>>(sumP, 512); k_zero<<<2, 256>>>(sumsqP, 512);
    { dim3 g(2, 256); k_stats_hl<<<g, 256>>>(aH0, aL0, N3, 512, sumP, sumsqP); }
    k_bn_params<<<2, 256>>>(sumP, sumsqP, 1.f / (float)N3, bn3g, bn3b, 512, alphaP, deltaP);
    k_fold_split<<<(512 * 512 + 255) / 256, 256>>>(h4_w, alphaP, 512, 512, 512 * 512, wfh, wfl);
    k_fold_bias<<<2, 256>>>(h4_w, h4_b, deltaP, 512, 512, 512, bF);

    // stage 4: K=512, M=512, relu6
    { dim3 g((N3 + 127) / 128, 4);
      mma_gemm<<<g, 256, 65536>>>(aH0, aL0, wfh, wfl, bF, aH1, aL1,
                                  TT3, TT3, 512, 0, 512, 512, 512, N3, 6.f); }
    k_zero<<<2, 256>>>(sumP, 512); k_zero<<<2, 256>>>(sumsqP, 512);
    { dim3 g(2, 256); k_stats_hl<<<g, 256>>>(aH1, aL1, N3, 512, sumP, sumsqP); }
    k_bn_params<<<2, 256>>>(sumP, sumsqP, 1.f / (float)N3, bn4g, bn4b, 512, alphaP, deltaP);
    k_fold_split<<<(1500 * 512 + 255) / 256, 256>>>(h5_w, alphaP, 512, 512, 1500 * 512, wfh, wfl);
    k_fold_bias<<<(1500 + 255) / 256, 256>>>(h5_w, h5_b, deltaP, 512, 512, 1500, bF);

    // stage 5: K=512, M=1500, relu6
    { dim3 g((N3 + 127) / 128, 12);
      mma_gemm<<<g, 256, 65536>>>(aH1, aL1, wfh, wfl, bF, b5h, b5l,
                                  TT3, TT3, 512, 0, 512, 1500, 1500, N3, 6.f); }

    // bn5 + stats pooling
    k_zero<<<(BATCH * 1500 + 255) / 256, 256>>>(pcS, BATCH * 1500);
    k_zero<<<(BATCH * 1500 + 255) / 256, 256>>>(pcQ, BATCH * 1500);
    { dim3 g((1500 + 255) / 256, BATCH, 8); k_pcstats_hl<<<g, 256>>>(b5h, b5l, TT3, 1500, pcS, pcQ); }
    k_pool<<<(1500 + 255) / 256, 256>>>(pcS, pcQ, TT3, 1500, bn5g, bn5b, pool);

    // FC head
    k_fc<<<512, 128>>>(pool, l1_w, l1_b, fc1, 3000, 512);
    k_bnc<<<2, 256>>>(fc1, bn6g, bn6b, fc1n, 512);
    k_fc<<<512, 128>>>(fc1n, l2_w, l2_b, fc2, 512, 512);
    k_bnc<<<2, 256>>>(fc2, bn7g, bn7b, (float*)d_out, 512);
}

// round 12
// speedup vs baseline: 4.8913x; 1.1283x over previous
#include <cuda_runtime.h>
#include <cuda_bf16.h>
#include <math.h>
#include <stdint.h>

#define BATCH 32
#define TT0 2048
#define TT1 2044
#define TT2 2040
#define TT3 2034
#define N1 (BATCH*TT1)
#define N2 (BATCH*TT2)
#define N3 (BATCH*TT3)

// ---------------- scratch ----------------
__device__ __nv_bfloat16 g_xsh[(size_t)N1 * 128], g_xsl[(size_t)N1 * 128];
__device__ __nv_bfloat16 g_aH0[(size_t)N1 * 512], g_aL0[(size_t)N1 * 512];
__device__ __nv_bfloat16 g_aH1[(size_t)N1 * 512], g_aL1[(size_t)N1 * 512];
__device__ __nv_bfloat16 g_w1h[512 * 128], g_w1l[512 * 128];
__device__ __nv_bfloat16 g_wfh[512 * 1536], g_wfl[512 * 1536];
__device__ float g_wp2[512 * 1536], g_wp3[512 * 1536];
__device__ float g_bF[1500];
__device__ float g_sum[512], g_sumsq[512], g_alpha[512], g_delta[512];
__device__ float g_pcS[BATCH * 1500], g_pcQ[BATCH * 1500];
__device__ float g_pool[BATCH * 3000];
__device__ float g_fc1[BATCH * 512], g_fc1n[BATCH * 512], g_fc2[BATCH * 512];

// ---------------- prep / scalar kernels ----------------
__global__ void k_zero(float* p, int n) {
    int i = blockIdx.x * blockDim.x + threadIdx.x;
    if (i < n) p[i] = 0.f;
}
__device__ __forceinline__ void split_st(float v, __nv_bfloat16* ph, __nv_bfloat16* pl) {
    __nv_bfloat16 h = __float2bfloat16(v);
    *ph = h;
    *pl = __float2bfloat16(v - __bfloat162float(h));
}
__global__ void k_presplice(const float* __restrict__ x, __nv_bfloat16* __restrict__ xh,
                            __nv_bfloat16* __restrict__ xl) {
    int i = blockIdx.x * blockDim.x + threadIdx.x;
    if (i >= N1 * 128) return;
    int r = i >> 7, kk = i & 127;
    float v = 0.f;
    if (kk < 100) {
        int c = kk / 20, f = kk - c * 20;
        int b = r / TT1, t = r - b * TT1;
        v = x[((size_t)(b * TT0 + t + c)) * 20 + f];
    }
    split_st(v, &xh[i], &xl[i]);
}
__global__ void k_prepw1(const float* __restrict__ w, __nv_bfloat16* __restrict__ wh,
                         __nv_bfloat16* __restrict__ wl) {
    int i = blockIdx.x * blockDim.x + threadIdx.x;
    if (i >= 512 * 128) return;
    int m = i >> 7, kk = i & 127;
    float v = 0.f;
    if (kk < 100) {
        int c = kk / 20, f = kk - c * 20;
        v = w[m * 100 + f * 5 + c];
    }
    split_st(v, &wh[i], &wl[i]);
}
__global__ void k_permMK(const float* __restrict__ w, float* __restrict__ wP) {
    int i = blockIdx.x * blockDim.x + threadIdx.x;
    if (i >= 512 * 1536) return;
    int m = i / 1536, kp = i - m * 1536;
    int c = kp >> 9, f = kp & 511;
    wP[i] = w[m * 1536 + f * 3 + c];
}
__global__ void k_bn_params(const float* __restrict__ sum, const float* __restrict__ sumsq,
                            float invN, const float* __restrict__ gamma,
                            const float* __restrict__ beta, int F,
                            float* __restrict__ alpha, float* __restrict__ delta) {
    int f = blockIdx.x * blockDim.x + threadIdx.x;
    if (f >= F) return;
    float mean = sum[f] * invN;
    float var = sumsq[f] * invN - mean * mean;
    float a = rsqrtf(var + 1e-5f) * (gamma ? gamma[f] : 1.f);
    alpha[f] = a;
    delta[f] = (beta ? beta[f] : 0.f) - mean * a;
}
__global__ void k_fold_split(const float* __restrict__ wP, const float* __restrict__ alpha,
                             int F, int K, int MK, __nv_bfloat16* __restrict__ wh,
                             __nv_bfloat16* __restrict__ wl) {
    int i = blockIdx.x * blockDim.x + threadIdx.x;
    if (i >= MK) return;
    int k = i % K;
    split_st(wP[i] * alpha[k % F], &wh[i], &wl[i]);
}
__global__ void k_fold_bias(const float* __restrict__ wP, const float* __restrict__ b0,
                            const float* __restrict__ delta, int F, int K, int M,
                            float* __restrict__ bF) {
    int m = blockIdx.x * blockDim.x + threadIdx.x;
    if (m >= M) return;
    float acc = b0[m];
    for (int k = 0; k < K; k++) acc += wP[(size_t)m * K + k] * delta[k % F];
    bF[m] = acc;
}
__global__ void k_pool(const float* __restrict__ pcS, const float* __restrict__ pcQ,
                       int T, int M, const float* __restrict__ gamma,
                       const float* __restrict__ beta, float* __restrict__ pooled) {
    int c = blockIdx.x * blockDim.x + threadIdx.x;
    if (c >= M) return;
    float gs = 0.f, gq = 0.f;
    for (int b = 0; b < BATCH; b++) { gs += pcS[b * M + c]; gq += pcQ[b * M + c]; }
    float Nf = (float)(BATCH * T);
    float mean = gs / Nf;
    float var = gq / Nf - mean * mean;
    float a = rsqrtf(var + 1e-5f) * gamma[c];
    float bt = beta[c];
    float Tf = (float)T;
    for (int b = 0; b < BATCH; b++) {
        float S1 = pcS[b * M + c], S2 = pcQ[b * M + c];
        float mt = S1 / Tf;
        float vt = (S2 - S1 * S1 / Tf) / (Tf - 1.f);
        pooled[b * 2 * M + c] = (mt - mean) * a + bt;
        pooled[b * 2 * M + M + c] = sqrtf(fmaxf(vt, 0.f)) * fabsf(a);
    }
}
__global__ void k_fc(const float* __restrict__ X, const float* __restrict__ W,
                     const float* __restrict__ bias, float* __restrict__ Y, int K, int M) {
    __shared__ float red[4][32];
    int m = blockIdx.x, tid = threadIdx.x;
    float acc[BATCH];
#pragma unroll
    for (int b = 0; b < BATCH; b++) acc[b] = 0.f;
    for (int k = tid; k < K; k += blockDim.x) {
        float w = W[(size_t)m * K + k];
#pragma unroll
        for (int b = 0; b < BATCH; b++) acc[b] += X[b * K + k] * w;
    }
#pragma unroll
    for (int b = 0; b < BATCH; b++) {
        float v = acc[b];
#pragma unroll
        for (int o = 16; o; o >>= 1) v += __shfl_down_sync(0xffffffffu, v, o);
        if ((tid & 31) == 0) red[tid >> 5][b] = v;
    }
    __syncthreads();
    if (tid < BATCH) {
        float v = red[0][tid] + red[1][tid] + red[2][tid] + red[3][tid] + bias[m];
        Y[tid * M + m] = fminf(fmaxf(v, 0.f), 6.f);
    }
}
__global__ void k_bnc(const float* __restrict__ X, const float* __restrict__ gamma,
                      const float* __restrict__ beta, float* __restrict__ Y, int M) {
    int j = blockIdx.x * blockDim.x + threadIdx.x;
    if (j >= M) return;
    float s = 0.f, q = 0.f;
    for (int b = 0; b < BATCH; b++) { float v = X[b * M + j]; s += v; q += v * v; }
    float mean = s / (float)BATCH;
    float var = q / (float)BATCH - mean * mean;
    float sc = rsqrtf(var + 1e-5f) * gamma[j];
    for (int b = 0; b < BATCH; b++) Y[b * M + j] = (X[b * M + j] - mean) * sc + beta[j];
}

// ---------------- HMMA GEMM (m16n8k16 bf16, hi/lo 3-product) ----------------
// C[128x128] per CTA. BK=32, double-buffered cp.async. Fused epilogue stats:
// per-channel (bucketed by batch when statStride>0) sum/sumsq via warp
// reduce + atomics. outH==nullptr -> stats-only (no output write).
__device__ __forceinline__ uint32_t smem_u32(const void* p) {
    uint32_t a;
    asm("{ .reg .u64 t; cvta.to.shared.u64 t, %1; cvt.u32.u64 %0, t; }" : "=r"(a) : "l"(p));
    return a;
}
__device__ __forceinline__ void cpa(uint32_t dst, const void* src, uint32_t n) {
    asm volatile("cp.async.cg.shared.global [%0], [%1], 16, %2;" :: "r"(dst), "l"(src), "r"(n) : "memory");
}
#define LDM4(v, a) \
    asm volatile("ldmatrix.sync.aligned.m8n8.x4.shared.b16 {%0,%1,%2,%3}, [%4];" \
        : "=r"((v)[0]), "=r"((v)[1]), "=r"((v)[2]), "=r"((v)[3]) : "r"(a))
#define MMA(d, a, b0, b1) \
    asm volatile("mma.sync.aligned.m16n8k16.row.col.f32.bf16.bf16.f32 " \
        "{%0,%1,%2,%3}, {%4,%5,%6,%7}, {%8,%9}, {%0,%1,%2,%3};" \
        : "+f"((d)[0]), "+f"((d)[1]), "+f"((d)[2]), "+f"((d)[3]) \
        : "r"((a)[0]), "r"((a)[1]), "r"((a)[2]), "r"((a)[3]), "r"(b0), "r"(b1))

__global__ __launch_bounds__(256)
void mma_gemm(const __nv_bfloat16* __restrict__ inH, const __nv_bfloat16* __restrict__ inL,
              const __nv_bfloat16* __restrict__ wH, const __nv_bfloat16* __restrict__ wL,
              const float* __restrict__ bias,
              __nv_bfloat16* __restrict__ outH, __nv_bfloat16* __restrict__ outL,
              float* __restrict__ statS, float* __restrict__ statQ,
              int statT, int statStride,
              int Tin, int Tout, int F, int step,
              int Ktot, int Mtot, int Mstride, int Nrows, float actmax) {
    extern __shared__ char smem[];
    const uint32_t sb = smem_u32(smem);
    const int t = threadIdx.x;
    const int row0 = blockIdx.y * 128;     // row tile = y (cols adjacent in wave)
    const int colbase = blockIdx.x * 128;  // col tile = x
    const int NKC = Ktot >> 5, FC = F >> 5;

    // ---- loader mapping ----
    const int lr = t >> 2, kg = t & 3;
    int ra = row0 + lr, rb = row0 + lr + 64;
    bool va = ra < Nrows, vb = rb < Nrows;
    size_t aba = 0, abb = 0;
    if (va) { int b_ = ra / Tout; aba = (size_t)(b_ * Tin + (ra - b_ * Tout)) * F; }
    if (vb) { int b_ = rb / Tout; abb = (size_t)(b_ * Tin + (rb - b_ * Tout)) * F; }
    int na = colbase + lr, nb = colbase + lr + 64;
    bool wva = na < Mtot, wvb = nb < Mtot;
    size_t wba = wva ? (size_t)na * Ktot : 0, wbb = wvb ? (size_t)nb * Ktot : 0;
    const uint32_t swz = (uint32_t)((kg ^ ((lr >> 1) & 3)) << 4);
    const uint32_t dRa = sb + lr * 64 + swz, dRb = sb + (lr + 64) * 64 + swz;
    uint32_t vA = va ? 16u : 0u, vB = vb ? 16u : 0u, vWa = wva ? 16u : 0u, vWb = wvb ? 16u : 0u;

#define LOAD_CHUNK(kc, buf) do { \
        uint32_t bo = (uint32_t)(buf) << 15; \
        int c_ = (kc) / FC; \
        size_t ao = (size_t)c_ * step * F + (size_t)((kc) - c_ * FC) * 32 + kg * 8; \
        size_t wo = (size_t)(kc) * 32 + kg * 8; \
        cpa(dRa + bo,         inH + aba + ao, vA); \
        cpa(dRb + bo,         inH + abb + ao, vB); \
        cpa(dRa + 8192 + bo,  inL + aba + ao, vA); \
        cpa(dRb + 8192 + bo,  inL + abb + ao, vB); \
        cpa(dRa + 16384 + bo, wH + wba + wo, vWa); \
        cpa(dRb + 16384 + bo, wH + wbb + wo, vWb); \
        cpa(dRa + 24576 + bo, wL + wba + wo, vWa); \
        cpa(dRb + 24576 + bo, wL + wbb + wo, vWb); \
        asm volatile("cp.async.commit_group;" ::: "memory"); \
    } while (0)

    const int wid = t >> 5, lane = t & 31;
    const int wr = wid & 1, wc2 = wid >> 1;
    uint32_t aAd[4], wAd[2];
    {
        int rbase = wr * 64 + (lane & 15);
        int kg0 = lane >> 4;
#pragma unroll
        for (int mi = 0; mi < 4; mi++) {
            int rr = rbase + mi * 16;
            aAd[mi] = sb + rr * 64 + ((kg0 ^ ((rr >> 1) & 3)) << 4);
        }
        int nbase = wc2 * 32 + (lane & 7) + ((lane >> 4) << 3);
        int kgw = (lane >> 3) & 1;
#pragma unroll
        for (int cj = 0; cj < 2; cj++) {
            int nn = nbase + cj * 16;
            wAd[cj] = sb + 16384 + nn * 64 + ((kgw ^ ((nn >> 1) & 3)) << 4);
        }
    }

    float acc[4][4][4];
#pragma unroll
    for (int i = 0; i < 4; i++)
#pragma unroll
        for (int j = 0; j < 4; j++)
#pragma unroll
            for (int q = 0; q < 4; q++) acc[i][j][q] = 0.f;

    LOAD_CHUNK(0, 0);
    for (int kc = 0; kc < NKC; kc++) {
        asm volatile("cp.async.wait_group 0;" ::: "memory");
        __syncthreads();
        if (kc + 1 < NKC) LOAD_CHUNK(kc + 1, (kc + 1) & 1);
        uint32_t bo = (uint32_t)(kc & 1) << 15;
#pragma unroll
        for (int ks = 0; ks < 2; ks++) {
            uint32_t kx = (uint32_t)ks << 5;
            uint32_t ah[4][4], al[4][4], wh[2][4], wl[2][4];
#pragma unroll
            for (int mi = 0; mi < 4; mi++) {
                uint32_t ad = (aAd[mi] ^ kx) + bo;
                LDM4(ah[mi], ad);
                LDM4(al[mi], ad + 8192);
            }
#pragma unroll
            for (int cj = 0; cj < 2; cj++) {
                uint32_t ad = (wAd[cj] ^ kx) + bo;
                LDM4(wh[cj], ad);
                LDM4(wl[cj], ad + 8192);
            }
#pragma unroll
            for (int mi = 0; mi < 4; mi++)
#pragma unroll
                for (int nj = 0; nj < 4; nj++) {
                    int cj = nj >> 1, h = (nj & 1) << 1;
                    MMA(acc[mi][nj], ah[mi], wh[cj][h], wh[cj][h + 1]);
                    MMA(acc[mi][nj], ah[mi], wl[cj][h], wl[cj][h + 1]);
                    MMA(acc[mi][nj], al[mi], wh[cj][h], wh[cj][h + 1]);
                }
        }
    }

    // ---- fused epilogue: activation, optional store, stats reduce+atomics ----
    const int re = row0 + wr * 64 + (lane >> 2);
    const int ce = colbase + wc2 * 32 + ((lane & 3) << 1);
    const bool wantOut = (outH != nullptr);
    const int rb0 = row0 + wr * 64;
    const bool anyrow = rb0 < Nrows;
    const int rfirst = anyrow ? rb0 : 0;
    const int rlast = min(rb0 + 63, Nrows - 1);
    const int bb0 = rfirst / statT;
    const int bb1 = (rlast >= 0) ? (rlast / statT) : bb0;
    const int rsplit = (bb0 + 1) * statT;

#pragma unroll
    for (int nj = 0; nj < 4; nj++) {
        int m = ce + nj * 8;
        bool mok = (m < Mtot);
        float s0x = 0.f, s0y = 0.f, q0x = 0.f, q0y = 0.f;
        float s1x = 0.f, s1y = 0.f, q1x = 0.f, q1y = 0.f;
        if (mok) {
            float b0v = bias[m], b1v = bias[m + 1];
#pragma unroll
            for (int mi = 0; mi < 4; mi++) {
#pragma unroll
                for (int half = 0; half < 2; half++) {
                    int r = re + mi * 16 + half * 8;
                    if (r >= Nrows) continue;
                    float v0 = fminf(fmaxf(acc[mi][nj][half * 2] + b0v, 0.f), actmax);
                    float v1 = fminf(fmaxf(acc[mi][nj][half * 2 + 1] + b1v, 0.f), actmax);
                    if (r >= rsplit) { s1x += v0; q1x += v0 * v0; s1y += v1; q1y += v1 * v1; }
                    else            { s0x += v0; q0x += v0 * v0; s0y += v1; q0y += v1 * v1; }
                    if (wantOut) {
                        __nv_bfloat16 h0 = __float2bfloat16(v0), h1 = __float2bfloat16(v1);
                        __nv_bfloat16 l0 = __float2bfloat16(v0 - __bfloat162float(h0));
                        __nv_bfloat16 l1 = __float2bfloat16(v1 - __bfloat162float(h1));
                        size_t ob = (size_t)r * Mstride + m;
                        *(__nv_bfloat162*)(outH + ob) = __halves2bfloat162(h0, h1);
                        *(__nv_bfloat162*)(outL + ob) = __halves2bfloat162(l0, l1);
                    }
                }
            }
        }
        // warp reduce over the 8 lanes sharing this column pair (lane bits 2..4)
#pragma unroll
        for (int o = 4; o <= 16; o <<= 1) {
            s0x += __shfl_xor_sync(0xffffffffu, s0x, o);
            s0y += __shfl_xor_sync(0xffffffffu, s0y, o);
            q0x += __shfl_xor_sync(0xffffffffu, q0x, o);
            q0y += __shfl_xor_sync(0xffffffffu, q0y, o);
            s1x += __shfl_xor_sync(0xffffffffu, s1x, o);
            s1y += __shfl_xor_sync(0xffffffffu, s1y, o);
            q1x += __shfl_xor_sync(0xffffffffu, q1x, o);
            q1y += __shfl_xor_sync(0xffffffffu, q1y, o);
        }
        if (lane < 4 && anyrow) {
            int mm = colbase + wc2 * 32 + (lane << 1) + nj * 8;
            if (mm < Mtot) {
                int i0 = bb0 * statStride + mm;
                atomicAdd(&statS[i0], s0x);
                atomicAdd(&statS[i0 + 1], s0y);
                atomicAdd(&statQ[i0], q0x);
                atomicAdd(&statQ[i0 + 1], q0y);
                if (bb1 != bb0) {
                    int i1 = bb1 * statStride + mm;
                    atomicAdd(&statS[i1], s1x);
                    atomicAdd(&statS[i1 + 1], s1y);
                    atomicAdd(&statQ[i1], q1x);
                    atomicAdd(&statQ[i1 + 1], q1y);
                }
            }
        }
    }
#undef LOAD_CHUNK
}

// ---------------------------------------------------------------------------
extern "C" void kernel_launch(void* const* d_in, const int* in_sizes, int n_in,
                              void* d_out, int out_size) {
    (void)in_sizes; (void)n_in; (void)out_size;
    const float* x    = (const float*)d_in[0];
    const float* h1_w = (const float*)d_in[1];  const float* h1_b = (const float*)d_in[2];
    const float* h2_w = (const float*)d_in[3];  const float* h2_b = (const float*)d_in[4];
    const float* bn2g = (const float*)d_in[5];  const float* bn2b = (const float*)d_in[6];
    const float* h3_w = (const float*)d_in[7];  const float* h3_b = (const float*)d_in[8];
    const float* bn3g = (const float*)d_in[9];  const float* bn3b = (const float*)d_in[10];
    const float* h4_w = (const float*)d_in[11]; const float* h4_b = (const float*)d_in[12];
    const float* bn4g = (const float*)d_in[13]; const float* bn4b = (const float*)d_in[14];
    const float* h5_w = (const float*)d_in[15]; const float* h5_b = (const float*)d_in[16];
    const float* bn5g = (const float*)d_in[17]; const float* bn5b = (const float*)d_in[18];
    const float* l1_w = (const float*)d_in[19]; const float* l1_b = (const float*)d_in[20];
    const float* bn6g = (const float*)d_in[21]; const float* bn6b = (const float*)d_in[22];
    const float* l2_w = (const float*)d_in[23]; const float* l2_b = (const float*)d_in[24];
    const float* bn7g = (const float*)d_in[25]; const float* bn7b = (const float*)d_in[26];

    __nv_bfloat16 *xsh, *xsl, *aH0, *aL0, *aH1, *aL1, *w1h, *w1l, *wfh, *wfl;
    float *wp2, *wp3, *bF, *sumP, *sumsqP, *alphaP, *deltaP, *pcS, *pcQ, *pool, *fc1, *fc1n, *fc2;
    cudaGetSymbolAddress((void**)&xsh, g_xsh);   cudaGetSymbolAddress((void**)&xsl, g_xsl);
    cudaGetSymbolAddress((void**)&aH0, g_aH0);   cudaGetSymbolAddress((void**)&aL0, g_aL0);
    cudaGetSymbolAddress((void**)&aH1, g_aH1);   cudaGetSymbolAddress((void**)&aL1, g_aL1);
    cudaGetSymbolAddress((void**)&w1h, g_w1h);   cudaGetSymbolAddress((void**)&w1l, g_w1l);
    cudaGetSymbolAddress((void**)&wfh, g_wfh);   cudaGetSymbolAddress((void**)&wfl, g_wfl);
    cudaGetSymbolAddress((void**)&wp2, g_wp2);   cudaGetSymbolAddress((void**)&wp3, g_wp3);
    cudaGetSymbolAddress((void**)&bF, g_bF);
    cudaGetSymbolAddress((void**)&sumP, g_sum);  cudaGetSymbolAddress((void**)&sumsqP, g_sumsq);
    cudaGetSymbolAddress((void**)&alphaP, g_alpha); cudaGetSymbolAddress((void**)&deltaP, g_delta);
    cudaGetSymbolAddress((void**)&pcS, g_pcS);   cudaGetSymbolAddress((void**)&pcQ, g_pcQ);
    cudaGetSymbolAddress((void**)&pool, g_pool);
    cudaGetSymbolAddress((void**)&fc1, g_fc1);   cudaGetSymbolAddress((void**)&fc1n, g_fc1n);
    cudaGetSymbolAddress((void**)&fc2, g_fc2);

    cudaFuncSetAttribute(mma_gemm, cudaFuncAttributeMaxDynamicSharedMemorySize, 65536);
    const float BIG = 3.0e38f;

    // prep
    k_presplice<<<(N1 * 128 + 255) / 256, 256>>>(x, xsh, xsl);
    k_prepw1<<<(512 * 128 + 255) / 256, 256>>>(h1_w, w1h, w1l);
    k_permMK<<<(512 * 1536 + 255) / 256, 256>>>(h2_w, wp2);
    k_permMK<<<(512 * 1536 + 255) / 256, 256>>>(h3_w, wp3);

    // stage 1: K=128 (padded), M=512, relu; fused bn1 stats
    k_zero<<<2, 256>>>(sumP, 512); k_zero<<<2, 256>>>(sumsqP, 512);
    { dim3 g(4, N1 / 128);
      mma_gemm<<<g, 256, 65536>>>(xsh, xsl, w1h, w1l, h1_b, aH0, aL0,
                                  sumP, sumsqP, N1, 0,
                                  TT1, TT1, 128, 0, 128, 512, 512, N1, BIG); }
    k_bn_params<<<2, 256>>>(sumP, sumsqP, 1.f / (float)N1, nullptr, nullptr, 512, alphaP, deltaP);
    k_fold_split<<<(512 * 1536 + 255) / 256, 256>>>(wp2, alphaP, 512, 1536, 512 * 1536, wfh, wfl);
    k_fold_bias<<<2, 256>>>(wp2, h2_b, deltaP, 512, 1536, 512, bF);

    // stage 2: K=1536 (3x512, step 2), M=512, relu; fused bn2 stats
    k_zero<<<2, 256>>>(sumP, 512); k_zero<<<2, 256>>>(sumsqP, 512);
    { dim3 g(4, N2 / 128);
      mma_gemm<<<g, 256, 65536>>>(aH0, aL0, wfh, wfl, bF, aH1, aL1,
                                  sumP, sumsqP, N2, 0,
                                  TT1, TT2, 512, 2, 1536, 512, 512, N2, BIG); }
    k_bn_params<<<2, 256>>>(sumP, sumsqP, 1.f / (float)N2, bn2g, bn2b, 512, alphaP, deltaP);
    k_fold_split<<<(512 * 1536 + 255) / 256, 256>>>(wp3, alphaP, 512, 1536, 512 * 1536, wfh, wfl);
    k_fold_bias<<<2, 256>>>(wp3, h3_b, deltaP, 512, 1536, 512, bF);

    // stage 3: K=1536 (3x512, step 3), M=512, relu; fused bn3 stats
    k_zero<<<2, 256>>>(sumP, 512); k_zero<<<2, 256>>>(sumsqP, 512);
    { dim3 g(4, (N3 + 127) / 128);
      mma_gemm<<<g, 256, 65536>>>(aH1, aL1, wfh, wfl, bF, aH0, aL0,
                                  sumP, sumsqP, N3, 0,
                                  TT2, TT3, 512, 3, 1536, 512, 512, N3, BIG); }
    k_bn_params<<<2, 256>>>(sumP, sumsqP, 1.f / (float)N3, bn3g, bn3b, 512, alphaP, deltaP);
    k_fold_split<<<(512 * 512 + 255) / 256, 256>>>(h4_w, alphaP, 512, 512, 512 * 512, wfh, wfl);
    k_fold_bias<<<2, 256>>>(h4_w, h4_b, deltaP, 512, 512, 512, bF);

    // stage 4: K=512, M=512, relu6; fused bn4 stats
    k_zero<<<2, 256>>>(sumP, 512); k_zero<<<2, 256>>>(sumsqP, 512);
    { dim3 g(4, (N3 + 127) / 128);
      mma_gemm<<<g, 256, 65536>>>(aH0, aL0, wfh, wfl, bF, aH1, aL1,
                                  sumP, sumsqP, N3, 0,
                                  TT3, TT3, 512, 0, 512, 512, 512, N3, 6.f); }
    k_bn_params<<<2, 256>>>(sumP, sumsqP, 1.f / (float)N3, bn4g, bn4b, 512, alphaP, deltaP);
    k_fold_split<<<(1500 * 512 + 255) / 256, 256>>>(h5_w, alphaP, 512, 512, 1500 * 512, wfh, wfl);
    k_fold_bias<<<(1500 + 255) / 256, 256>>>(h5_w, h5_b, deltaP, 512, 512, 1500, bF);

    // stage 5: K=512, M=1500, relu6 — stats-only (no output write), per-(b,c)
    k_zero<<<(BATCH * 1500 + 255) / 256, 256>>>(pcS, BATCH * 1500);
    k_zero<<<(BATCH * 1500 + 255) / 256, 256>>>(pcQ, BATCH * 1500);
    { dim3 g(12, (N3 + 127) / 128);
      mma_gemm<<<g, 256, 65536>>>(aH1, aL1, wfh, wfl, bF, nullptr, nullptr,
                                  pcS, pcQ, TT3, 1500,
                                  TT3, TT3, 512, 0, 512, 1500, 1500, N3, 6.f); }
    k_pool<<<(1500 + 255) / 256, 256>>>(pcS, pcQ, TT3, 1500, bn5g, bn5b, pool);

    // FC head
    k_fc<<<512, 128>>>(pool, l1_w, l1_b, fc1, 3000, 512);
    k_bnc<<<2, 256>>>(fc1, bn6g, bn6b, fc1n, 512);
    k_fc<<<512, 128>>>(fc1n, l2_w, l2_b, fc2, 512, 512);
    k_bnc<<<2, 256>>>(fc2, bn7g, bn7b, (float*)d_out, 512);
}

// round 14
// speedup vs baseline: 5.4044x; 1.1049x over previous
#include <cuda_runtime.h>
#include <cuda_bf16.h>
#include <math.h>
#include <stdint.h>

#define BATCH 32
#define TT0 2048
#define TT1 2044
#define TT2 2040
#define TT3 2034
#define N1 (BATCH*TT1)
#define N2 (BATCH*TT2)
#define N3 (BATCH*TT3)

// ---------------- scratch ----------------
__device__ __nv_bfloat16 g_xsh[(size_t)N1 * 128], g_xsl[(size_t)N1 * 128];
__device__ __nv_bfloat16 g_aH0[(size_t)N1 * 512], g_aL0[(size_t)N1 * 512];
__device__ __nv_bfloat16 g_aH1[(size_t)N1 * 512], g_aL1[(size_t)N1 * 512];
__device__ __nv_bfloat16 g_w1h[512 * 128], g_w1l[512 * 128];
__device__ __nv_bfloat16 g_wfh[512 * 1536], g_wfl[512 * 1536];
__device__ float g_wp2[512 * 1536], g_wp3[512 * 1536];
__device__ float g_bF[1500];
__device__ float g_sum[512], g_sumsq[512], g_alpha[512], g_delta[512];
__device__ float g_pcS[BATCH * 1500], g_pcQ[BATCH * 1500];
__device__ float g_pool[BATCH * 3000];
__device__ float g_fc1[BATCH * 512], g_fc1n[BATCH * 512], g_fc2[BATCH * 512];

// ---------------- prep / scalar kernels ----------------
__global__ void k_zero(float* p, int n) {
    int i = blockIdx.x * blockDim.x + threadIdx.x;
    if (i < n) p[i] = 0.f;
}
__device__ __forceinline__ void split_st(float v, __nv_bfloat16* ph, __nv_bfloat16* pl) {
    __nv_bfloat16 h = __float2bfloat16(v);
    *ph = h;
    *pl = __float2bfloat16(v - __bfloat162float(h));
}
__global__ void k_presplice(const float* __restrict__ x, __nv_bfloat16* __restrict__ xh,
                            __nv_bfloat16* __restrict__ xl) {
    int i = blockIdx.x * blockDim.x + threadIdx.x;
    if (i >= N1 * 128) return;
    int r = i >> 7, kk = i & 127;
    float v = 0.f;
    if (kk < 100) {
        int c = kk / 20, f = kk - c * 20;
        int b = r / TT1, t = r - b * TT1;
        v = x[((size_t)(b * TT0 + t + c)) * 20 + f];
    }
    split_st(v, &xh[i], &xl[i]);
}
__global__ void k_prepw1(const float* __restrict__ w, __nv_bfloat16* __restrict__ wh,
                         __nv_bfloat16* __restrict__ wl) {
    int i = blockIdx.x * blockDim.x + threadIdx.x;
    if (i >= 512 * 128) return;
    int m = i >> 7, kk = i & 127;
    float v = 0.f;
    if (kk < 100) {
        int c = kk / 20, f = kk - c * 20;
        v = w[m * 100 + f * 5 + c];
    }
    split_st(v, &wh[i], &wl[i]);
}
__global__ void k_permMK(const float* __restrict__ w, float* __restrict__ wP) {
    int i = blockIdx.x * blockDim.x + threadIdx.x;
    if (i >= 512 * 1536) return;
    int m = i / 1536, kp = i - m * 1536;
    int c = kp >> 9, f = kp & 511;
    wP[i] = w[m * 1536 + f * 3 + c];
}
__global__ void k_bn_params(const float* __restrict__ sum, const float* __restrict__ sumsq,
                            float invN, const float* __restrict__ gamma,
                            const float* __restrict__ beta, int F,
                            float* __restrict__ alpha, float* __restrict__ delta) {
    int f = blockIdx.x * blockDim.x + threadIdx.x;
    if (f >= F) return;
    float mean = sum[f] * invN;
    float var = sumsq[f] * invN - mean * mean;
    float a = rsqrtf(var + 1e-5f) * (gamma ? gamma[f] : 1.f);
    alpha[f] = a;
    delta[f] = (beta ? beta[f] : 0.f) - mean * a;
}
__global__ void k_fold_split(const float* __restrict__ wP, const float* __restrict__ alpha,
                             int F, int K, int MK, __nv_bfloat16* __restrict__ wh,
                             __nv_bfloat16* __restrict__ wl) {
    int i = blockIdx.x * blockDim.x + threadIdx.x;
    if (i >= MK) return;
    int k = i % K;
    split_st(wP[i] * alpha[k % F], &wh[i], &wl[i]);
}
__global__ void k_fold_bias(const float* __restrict__ wP, const float* __restrict__ b0,
                            const float* __restrict__ delta, int F, int K, int M,
                            float* __restrict__ bF) {
    int m = blockIdx.x * blockDim.x + threadIdx.x;
    if (m >= M) return;
    float acc = b0[m];
    for (int k = 0; k < K; k++) acc += wP[(size_t)m * K + k] * delta[k % F];
    bF[m] = acc;
}
__global__ void k_pool(const float* __restrict__ pcS, const float* __restrict__ pcQ,
                       int T, int M, const float* __restrict__ gamma,
                       const float* __restrict__ beta, float* __restrict__ pooled) {
    int c = blockIdx.x * blockDim.x + threadIdx.x;
    if (c >= M) return;
    float gs = 0.f, gq = 0.f;
    for (int b = 0; b < BATCH; b++) { gs += pcS[b * M + c]; gq += pcQ[b * M + c]; }
    float Nf = (float)(BATCH * T);
    float mean = gs / Nf;
    float var = gq / Nf - mean * mean;
    float a = rsqrtf(var + 1e-5f) * gamma[c];
    float bt = beta[c];
    float Tf = (float)T;
    for (int b = 0; b < BATCH; b++) {
        float S1 = pcS[b * M + c], S2 = pcQ[b * M + c];
        float mt = S1 / Tf;
        float vt = (S2 - S1 * S1 / Tf) / (Tf - 1.f);
        pooled[b * 2 * M + c] = (mt - mean) * a + bt;
        pooled[b * 2 * M + M + c] = sqrtf(fmaxf(vt, 0.f)) * fabsf(a);
    }
}
__global__ void k_fc(const float* __restrict__ X, const float* __restrict__ W,
                     const float* __restrict__ bias, float* __restrict__ Y, int K, int M) {
    __shared__ float red[4][32];
    int m = blockIdx.x, tid = threadIdx.x;
    float acc[BATCH];
#pragma unroll
    for (int b = 0; b < BATCH; b++) acc[b] = 0.f;
    for (int k = tid; k < K; k += blockDim.x) {
        float w = W[(size_t)m * K + k];
#pragma unroll
        for (int b = 0; b < BATCH; b++) acc[b] += X[b * K + k] * w;
    }
#pragma unroll
    for (int b = 0; b < BATCH; b++) {
        float v = acc[b];
#pragma unroll
        for (int o = 16; o; o >>= 1) v += __shfl_down_sync(0xffffffffu, v, o);
        if ((tid & 31) == 0) red[tid >> 5][b] = v;
    }
    __syncthreads();
    if (tid < BATCH) {
        float v = red[0][tid] + red[1][tid] + red[2][tid] + red[3][tid] + bias[m];
        Y[tid * M + m] = fminf(fmaxf(v, 0.f), 6.f);
    }
}
__global__ void k_bnc(const float* __restrict__ X, const float* __restrict__ gamma,
                      const float* __restrict__ beta, float* __restrict__ Y, int M) {
    int j = blockIdx.x * blockDim.x + threadIdx.x;
    if (j >= M) return;
    float s = 0.f, q = 0.f;
    for (int b = 0; b < BATCH; b++) { float v = X[b * M + j]; s += v; q += v * v; }
    float mean = s / (float)BATCH;
    float var = q / (float)BATCH - mean * mean;
    float sc = rsqrtf(var + 1e-5f) * gamma[j];
    for (int b = 0; b < BATCH; b++) Y[b * M + j] = (X[b * M + j] - mean) * sc + beta[j];
}

// ---------------- HMMA GEMM (m16n8k16 bf16, hi/lo 3-product) ----------------
// C[128 x 256] per CTA, 8 warps as 2(row)x4(col), warp tile 64x64. BK=32,
// double-buffered cp.async. SMEM stage (48KB): Ah@0 Al@8192 Wh@16384 Wl@32768.
// Fused epilogue stats; outH==nullptr -> stats-only.
__device__ __forceinline__ uint32_t smem_u32(const void* p) {
    uint32_t a;
    asm("{ .reg .u64 t; cvta.to.shared.u64 t, %1; cvt.u32.u64 %0, t; }" : "=r"(a) : "l"(p));
    return a;
}
__device__ __forceinline__ void cpa(uint32_t dst, const void* src, uint32_t n) {
    asm volatile("cp.async.cg.shared.global [%0], [%1], 16, %2;" :: "r"(dst), "l"(src), "r"(n) : "memory");
}
#define LDM4(v, a) \
    asm volatile("ldmatrix.sync.aligned.m8n8.x4.shared.b16 {%0,%1,%2,%3}, [%4];" \
        : "=r"((v)[0]), "=r"((v)[1]), "=r"((v)[2]), "=r"((v)[3]) : "r"(a))
#define MMA(d, a, b0, b1) \
    asm volatile("mma.sync.aligned.m16n8k16.row.col.f32.bf16.bf16.f32 " \
        "{%0,%1,%2,%3}, {%4,%5,%6,%7}, {%8,%9}, {%0,%1,%2,%3};" \
        : "+f"((d)[0]), "+f"((d)[1]), "+f"((d)[2]), "+f"((d)[3]) \
        : "r"((a)[0]), "r"((a)[1]), "r"((a)[2]), "r"((a)[3]), "r"(b0), "r"(b1))

#define STG_SZ 49152

__global__ __launch_bounds__(256)
void mma_gemm(const __nv_bfloat16* __restrict__ inH, const __nv_bfloat16* __restrict__ inL,
              const __nv_bfloat16* __restrict__ wH, const __nv_bfloat16* __restrict__ wL,
              const float* __restrict__ bias,
              __nv_bfloat16* __restrict__ outH, __nv_bfloat16* __restrict__ outL,
              float* __restrict__ statS, float* __restrict__ statQ,
              int statT, int statStride,
              int Tin, int Tout, int F, int step,
              int Ktot, int Mtot, int Mstride, int Nrows, float actmax) {
    extern __shared__ char smem[];
    const uint32_t sb = smem_u32(smem);
    const int t = threadIdx.x;
    const int row0 = blockIdx.y * 128;
    const int colbase = blockIdx.x * 256;
    const int NKC = Ktot >> 5, FC = F >> 5;

    // ---- loader mapping ----
    const int lr = t >> 2, kg = t & 3;                    // lr 0..63
    int ra = row0 + lr, rb = row0 + lr + 64;
    bool va = ra < Nrows, vb = rb < Nrows;
    size_t aba = 0, abb = 0;
    if (va) { int b_ = ra / Tout; aba = (size_t)(b_ * Tin + (ra - b_ * Tout)) * F; }
    if (vb) { int b_ = rb / Tout; abb = (size_t)(b_ * Tin + (rb - b_ * Tout)) * F; }
    const uint32_t swz = (uint32_t)((kg ^ ((lr >> 1) & 3)) << 4);
    const uint32_t dA0 = sb + lr * 64 + swz;
    const uint32_t dA1 = sb + (lr + 64) * 64 + swz;
    uint32_t vA0 = va ? 16u : 0u, vA1 = vb ? 16u : 0u;
    // W: 4 rows per part: lr + 64*j
    size_t wb[4]; uint32_t vW[4], dW[4];
#pragma unroll
    for (int j = 0; j < 4; j++) {
        int n = colbase + lr + 64 * j;
        bool ok = n < Mtot;
        vW[j] = ok ? 16u : 0u;
        wb[j] = ok ? (size_t)n * Ktot : 0;
        dW[j] = sb + 16384 + (lr + 64 * j) * 64 + swz;
    }

#define LOAD_CHUNK(kc, buf) do { \
        uint32_t bo = (uint32_t)(buf) * STG_SZ; \
        int c_ = (kc) / FC; \
        size_t ao = (size_t)c_ * step * F + (size_t)((kc) - c_ * FC) * 32 + kg * 8; \
        size_t wo = (size_t)(kc) * 32 + kg * 8; \
        cpa(dA0 + bo,        inH + aba + ao, vA0); \
        cpa(dA1 + bo,        inH + abb + ao, vA1); \
        cpa(dA0 + 8192 + bo, inL + aba + ao, vA0); \
        cpa(dA1 + 8192 + bo, inL + abb + ao, vA1); \
        _Pragma("unroll") \
        for (int j = 0; j < 4; j++) { \
            cpa(dW[j] + bo,         wH + wb[j] + wo, vW[j]); \
            cpa(dW[j] + 16384 + bo, wL + wb[j] + wo, vW[j]); \
        } \
        asm volatile("cp.async.commit_group;" ::: "memory"); \
    } while (0)

    // ---- compute mapping: warp (wr, wc) -> rows wr*64+, cols wc*64+ ----
    const int wid = t >> 5, lane = t & 31;
    const int wr = wid & 1, wc = wid >> 1;
    uint32_t aAd[4], wAd[4];
    {
        int rbase = wr * 64 + (lane & 15);
        int kg0 = lane >> 4;
#pragma unroll
        for (int mi = 0; mi < 4; mi++) {
            int rr = rbase + mi * 16;
            aAd[mi] = sb + rr * 64 + ((kg0 ^ ((rr >> 1) & 3)) << 4);
        }
        int kgw = (lane >> 3) & 1;
#pragma unroll
        for (int cj = 0; cj < 4; cj++) {
            int nn = wc * 64 + cj * 16 + (lane & 7) + ((lane >> 4) << 3);
            wAd[cj] = sb + 16384 + nn * 64 + ((kgw ^ ((nn >> 1) & 3)) << 4);
        }
    }

    float acc[4][8][4];
#pragma unroll
    for (int i = 0; i < 4; i++)
#pragma unroll
        for (int j = 0; j < 8; j++)
#pragma unroll
            for (int q = 0; q < 4; q++) acc[i][j][q] = 0.f;

    LOAD_CHUNK(0, 0);
    for (int kc = 0; kc < NKC; kc++) {
        asm volatile("cp.async.wait_group 0;" ::: "memory");
        __syncthreads();
        if (kc + 1 < NKC) LOAD_CHUNK(kc + 1, (kc + 1) & 1);
        uint32_t bo = (uint32_t)(kc & 1) * STG_SZ;
#pragma unroll
        for (int ks = 0; ks < 2; ks++) {
            uint32_t kx = (uint32_t)ks << 5;
            uint32_t ah[4][4], al[4][4];
#pragma unroll
            for (int mi = 0; mi < 4; mi++) {
                uint32_t ad = (aAd[mi] ^ kx) + bo;
                LDM4(ah[mi], ad);
                LDM4(al[mi], ad + 8192);
            }
#pragma unroll
            for (int cj = 0; cj < 4; cj++) {
                uint32_t wh[4], wl[4];
                uint32_t ad = (wAd[cj] ^ kx) + bo;
                LDM4(wh, ad);
                LDM4(wl, ad + 16384);
#pragma unroll
                for (int mi = 0; mi < 4; mi++) {
#pragma unroll
                    for (int njl = 0; njl < 2; njl++) {
                        int nj = cj * 2 + njl, h = njl << 1;
                        MMA(acc[mi][nj], ah[mi], wh[h], wh[h + 1]);
                        MMA(acc[mi][nj], ah[mi], wl[h], wl[h + 1]);
                        MMA(acc[mi][nj], al[mi], wh[h], wh[h + 1]);
                    }
                }
            }
        }
    }

    // ---- fused epilogue ----
    const int re = row0 + wr * 64 + (lane >> 2);
    const int ce = colbase + wc * 64 + ((lane & 3) << 1);
    const bool wantOut = (outH != nullptr);
    const int rb0 = row0 + wr * 64;
    const bool anyrow = rb0 < Nrows;
    const int rfirst = anyrow ? rb0 : 0;
    const int rlast = min(rb0 + 63, Nrows - 1);
    const int bb0 = rfirst / statT;
    const int bb1 = (rlast >= 0) ? (rlast / statT) : bb0;
    const int rsplit = (bb0 + 1) * statT;

#pragma unroll
    for (int nj = 0; nj < 8; nj++) {
        int m = ce + nj * 8;
        bool mok = (m < Mtot);
        float s0x = 0.f, s0y = 0.f, q0x = 0.f, q0y = 0.f;
        float s1x = 0.f, s1y = 0.f, q1x = 0.f, q1y = 0.f;
        if (mok) {
            float b0v = bias[m], b1v = bias[m + 1];
#pragma unroll
            for (int mi = 0; mi < 4; mi++) {
#pragma unroll
                for (int half = 0; half < 2; half++) {
                    int r = re + mi * 16 + half * 8;
                    if (r >= Nrows) continue;
                    float v0 = fminf(fmaxf(acc[mi][nj][half * 2] + b0v, 0.f), actmax);
                    float v1 = fminf(fmaxf(acc[mi][nj][half * 2 + 1] + b1v, 0.f), actmax);
                    if (r >= rsplit) { s1x += v0; q1x += v0 * v0; s1y += v1; q1y += v1 * v1; }
                    else            { s0x += v0; q0x += v0 * v0; s0y += v1; q0y += v1 * v1; }
                    if (wantOut) {
                        __nv_bfloat16 h0 = __float2bfloat16(v0), h1 = __float2bfloat16(v1);
                        __nv_bfloat16 l0 = __float2bfloat16(v0 - __bfloat162float(h0));
                        __nv_bfloat16 l1 = __float2bfloat16(v1 - __bfloat162float(h1));
                        size_t ob = (size_t)r * Mstride + m;
                        *(__nv_bfloat162*)(outH + ob) = __halves2bfloat162(h0, h1);
                        *(__nv_bfloat162*)(outL + ob) = __halves2bfloat162(l0, l1);
                    }
                }
            }
        }
#pragma unroll
        for (int o = 4; o <= 16; o <<= 1) {
            s0x += __shfl_xor_sync(0xffffffffu, s0x, o);
            s0y += __shfl_xor_sync(0xffffffffu, s0y, o);
            q0x += __shfl_xor_sync(0xffffffffu, q0x, o);
            q0y += __shfl_xor_sync(0xffffffffu, q0y, o);
            s1x += __shfl_xor_sync(0xffffffffu, s1x, o);
            s1y += __shfl_xor_sync(0xffffffffu, s1y, o);
            q1x += __shfl_xor_sync(0xffffffffu, q1x, o);
            q1y += __shfl_xor_sync(0xffffffffu, q1y, o);
        }
        if (lane < 4 && anyrow) {
            int mm = colbase + wc * 64 + (lane << 1) + nj * 8;
            if (mm < Mtot) {
                int i0 = bb0 * statStride + mm;
                atomicAdd(&statS[i0], s0x);
                atomicAdd(&statS[i0 + 1], s0y);
                atomicAdd(&statQ[i0], q0x);
                atomicAdd(&statQ[i0 + 1], q0y);
                if (bb1 != bb0) {
                    int i1 = bb1 * statStride + mm;
                    atomicAdd(&statS[i1], s1x);
                    atomicAdd(&statS[i1 + 1], s1y);
                    atomicAdd(&statQ[i1], q1x);
                    atomicAdd(&statQ[i1 + 1], q1y);
                }
            }
        }
    }
#undef LOAD_CHUNK
}

// ---------------------------------------------------------------------------
extern "C" void kernel_launch(void* const* d_in, const int* in_sizes, int n_in,
                              void* d_out, int out_size) {
    (void)in_sizes; (void)n_in; (void)out_size;
    const float* x    = (const float*)d_in[0];
    const float* h1_w = (const float*)d_in[1];  const float* h1_b = (const float*)d_in[2];
    const float* h2_w = (const float*)d_in[3];  const float* h2_b = (const float*)d_in[4];
    const float* bn2g = (const float*)d_in[5];  const float* bn2b = (const float*)d_in[6];
    const float* h3_w = (const float*)d_in[7];  const float* h3_b = (const float*)d_in[8];
    const float* bn3g = (const float*)d_in[9];  const float* bn3b = (const float*)d_in[10];
    const float* h4_w = (const float*)d_in[11]; const float* h4_b = (const float*)d_in[12];
    const float* bn4g = (const float*)d_in[13]; const float* bn4b = (const float*)d_in[14];
    const float* h5_w = (const float*)d_in[15]; const float* h5_b = (const float*)d_in[16];
    const float* bn5g = (const float*)d_in[17]; const float* bn5b = (const float*)d_in[18];
    const float* l1_w = (const float*)d_in[19]; const float* l1_b = (const float*)d_in[20];
    const float* bn6g = (const float*)d_in[21]; const float* bn6b = (const float*)d_in[22];
    const float* l2_w = (const float*)d_in[23]; const float* l2_b = (const float*)d_in[24];
    const float* bn7g = (const float*)d_in[25]; const float* bn7b = (const float*)d_in[26];

    __nv_bfloat16 *xsh, *xsl, *aH0, *aL0, *aH1, *aL1, *w1h, *w1l, *wfh, *wfl;
    float *wp2, *wp3, *bF, *sumP, *sumsqP, *alphaP, *deltaP, *pcS, *pcQ, *pool, *fc1, *fc1n, *fc2;
    cudaGetSymbolAddress((void**)&xsh, g_xsh);   cudaGetSymbolAddress((void**)&xsl, g_xsl);
    cudaGetSymbolAddress((void**)&aH0, g_aH0);   cudaGetSymbolAddress((void**)&aL0, g_aL0);
    cudaGetSymbolAddress((void**)&aH1, g_aH1);   cudaGetSymbolAddress((void**)&aL1, g_aL1);
    cudaGetSymbolAddress((void**)&w1h, g_w1h);   cudaGetSymbolAddress((void**)&w1l, g_w1l);
    cudaGetSymbolAddress((void**)&wfh, g_wfh);   cudaGetSymbolAddress((void**)&wfl, g_wfl);
    cudaGetSymbolAddress((void**)&wp2, g_wp2);   cudaGetSymbolAddress((void**)&wp3, g_wp3);
    cudaGetSymbolAddress((void**)&bF, g_bF);
    cudaGetSymbolAddress((void**)&sumP, g_sum);  cudaGetSymbolAddress((void**)&sumsqP, g_sumsq);
    cudaGetSymbolAddress((void**)&alphaP, g_alpha); cudaGetSymbolAddress((void**)&deltaP, g_delta);
    cudaGetSymbolAddress((void**)&pcS, g_pcS);   cudaGetSymbolAddress((void**)&pcQ, g_pcQ);
    cudaGetSymbolAddress((void**)&pool, g_pool);
    cudaGetSymbolAddress((void**)&fc1, g_fc1);   cudaGetSymbolAddress((void**)&fc1n, g_fc1n);
    cudaGetSymbolAddress((void**)&fc2, g_fc2);

    cudaFuncSetAttribute(mma_gemm, cudaFuncAttributeMaxDynamicSharedMemorySize, 2 * STG_SZ);
    const float BIG = 3.0e38f;

    // prep — ordered so launch #6 (ncu -s 5 -c 1 capture slot) is mma_gemm stage 1
    k_presplice<<<(N1 * 128 + 255) / 256, 256>>>(x, xsh, xsl);          // 1
    k_prepw1<<<(512 * 128 + 255) / 256, 256>>>(h1_w, w1h, w1l);         // 2
    k_zero<<<2, 256>>>(sumP, 512);                                       // 3
    k_zero<<<2, 256>>>(sumsqP, 512);                                     // 4
    k_permMK<<<(512 * 1536 + 255) / 256, 256>>>(h2_w, wp2);             // 5

    // stage 1: K=128 (padded), M=512, relu; fused bn1 stats               6
    { dim3 g(2, N1 / 128);
      mma_gemm<<<g, 256, 2 * STG_SZ>>>(xsh, xsl, w1h, w1l, h1_b, aH0, aL0,
                                       sumP, sumsqP, N1, 0,
                                       TT1, TT1, 128, 0, 128, 512, 512, N1, BIG); }
    k_permMK<<<(512 * 1536 + 255) / 256, 256>>>(h3_w, wp3);
    k_bn_params<<<2, 256>>>(sumP, sumsqP, 1.f / (float)N1, nullptr, nullptr, 512, alphaP, deltaP);
    k_fold_split<<<(512 * 1536 + 255) / 256, 256>>>(wp2, alphaP, 512, 1536, 512 * 1536, wfh, wfl);
    k_fold_bias<<<2, 256>>>(wp2, h2_b, deltaP, 512, 1536, 512, bF);

    // stage 2: K=1536 (3x512, step 2), M=512, relu; fused bn2 stats
    k_zero<<<2, 256>>>(sumP, 512); k_zero<<<2, 256>>>(sumsqP, 512);
    { dim3 g(2, N2 / 128);
      mma_gemm<<<g, 256, 2 * STG_SZ>>>(aH0, aL0, wfh, wfl, bF, aH1, aL1,
                                       sumP, sumsqP, N2, 0,
                                       TT1, TT2, 512, 2, 1536, 512, 512, N2, BIG); }
    k_bn_params<<<2, 256>>>(sumP, sumsqP, 1.f / (float)N2, bn2g, bn2b, 512, alphaP, deltaP);
    k_fold_split<<<(512 * 1536 + 255) / 256, 256>>>(wp3, alphaP, 512, 1536, 512 * 1536, wfh, wfl);
    k_fold_bias<<<2, 256>>>(wp3, h3_b, deltaP, 512, 1536, 512, bF);

    // stage 3: K=1536 (3x512, step 3), M=512, relu; fused bn3 stats
    k_zero<<<2, 256>>>(sumP, 512); k_zero<<<2, 256>>>(sumsqP, 512);
    { dim3 g(2, (N3 + 127) / 128);
      mma_gemm<<<g, 256, 2 * STG_SZ>>>(aH1, aL1, wfh, wfl, bF, aH0, aL0,
                                       sumP, sumsqP, N3, 0,
                                       TT2, TT3, 512, 3, 1536, 512, 512, N3, BIG); }
    k_bn_params<<<2, 256>>>(sumP, sumsqP, 1.f / (float)N3, bn3g, bn3b, 512, alphaP, deltaP);
    k_fold_split<<<(512 * 512 + 255) / 256, 256>>>(h4_w, alphaP, 512, 512, 512 * 512, wfh, wfl);
    k_fold_bias<<<2, 256>>>(h4_w, h4_b, deltaP, 512, 512, 512, bF);

    // stage 4: K=512, M=512, relu6; fused bn4 stats
    k_zero<<<2, 256>>>(sumP, 512); k_zero<<<2, 256>>>(sumsqP, 512);
    { dim3 g(2, (N3 + 127) / 128);
      mma_gemm<<<g, 256, 2 * STG_SZ>>>(aH0, aL0, wfh, wfl, bF, aH1, aL1,
                                       sumP, sumsqP, N3, 0,
                                       TT3, TT3, 512, 0, 512, 512, 512, N3, 6.f); }
    k_bn_params<<<2, 256>>>(sumP, sumsqP, 1.f / (float)N3, bn4g, bn4b, 512, alphaP, deltaP);
    k_fold_split<<<(1500 * 512 + 255) / 256, 256>>>(h5_w, alphaP, 512, 512, 1500 * 512, wfh, wfl);
    k_fold_bias<<<(1500 + 255) / 256, 256>>>(h5_w, h5_b, deltaP, 512, 512, 1500, bF);

    // stage 5: K=512, M=1500, relu6 — stats-only, per-(b,c)
    k_zero<<<(BATCH * 1500 + 255) / 256, 256>>>(pcS, BATCH * 1500);
    k_zero<<<(BATCH * 1500 + 255) / 256, 256>>>(pcQ, BATCH * 1500);
    { dim3 g(6, (N3 + 127) / 128);
      mma_gemm<<<g, 256, 2 * STG_SZ>>>(aH1, aL1, wfh, wfl, bF, nullptr, nullptr,
                                       pcS, pcQ, TT3, 1500,
                                       TT3, TT3, 512, 0, 512, 1500, 1500, N3, 6.f); }
    k_pool<<<(1500 + 255) / 256, 256>>>(pcS, pcQ, TT3, 1500, bn5g, bn5b, pool);

    // FC head
    k_fc<<<512, 128>>>(pool, l1_w, l1_b, fc1, 3000, 512);
    k_bnc<<<2, 256>>>(fc1, bn6g, bn6b, fc1n, 512);
    k_fc<<<512, 128>>>(fc1n, l2_w, l2_b, fc2, 512, 512);
    k_bnc<<<2, 256>>>(fc2, bn7g, bn7b, (float*)d_out, 512);
}